// round 3
// baseline (speedup 1.0000x reference)
#include <cuda_runtime.h>
#include <math.h>

#define NSEQ 256
#define CZ   128
#define NHEAD 4
#define CHEAD 32
#define NROWS (NSEQ*NSEQ)   // 65536

// ---------------- scratch (static __device__, no allocation) ----------------
__device__ float g_zn  [(size_t)NROWS * CZ];        // LN(z)           33.5 MB
__device__ float g_qkv [(size_t)NROWS * 3 * CZ];    // q|k|v           100 MB
__device__ float g_gate[(size_t)NROWS * CZ];        // sigmoid(z@Wg)   33.5 MB
__device__ float g_bias[(size_t)NHEAD * NROWS];     // [h][row]        1 MB
__device__ float g_go  [(size_t)NROWS * CZ];        // gate * o        33.5 MB

// ---------------- LayerNorm: one warp per 128-float row ----------------
__global__ __launch_bounds__(256) void ln_kernel(const float* __restrict__ z,
                                                 const float* __restrict__ gam,
                                                 const float* __restrict__ bet)
{
    int row  = (blockIdx.x * blockDim.x + threadIdx.x) >> 5;
    int lane = threadIdx.x & 31;
    float4 v = *(const float4*)(z + (size_t)row * CZ + lane * 4);
    float s  = v.x + v.y + v.z + v.w;
    float ss = v.x*v.x + v.y*v.y + v.z*v.z + v.w*v.w;
    #pragma unroll
    for (int m = 16; m; m >>= 1) {
        s  += __shfl_xor_sync(0xffffffffu, s,  m);
        ss += __shfl_xor_sync(0xffffffffu, ss, m);
    }
    float mu   = s * (1.0f / CZ);
    float var  = ss * (1.0f / CZ) - mu * mu;
    float rstd = rsqrtf(var + 1e-5f);
    float4 gg = *(const float4*)(gam + lane * 4);
    float4 bb = *(const float4*)(bet + lane * 4);
    float4 o;
    o.x = (v.x - mu) * rstd * gg.x + bb.x;
    o.y = (v.y - mu) * rstd * gg.y + bb.y;
    o.z = (v.z - mu) * rstd * gg.z + bb.z;
    o.w = (v.w - mu) * rstd * gg.w + bb.w;
    *(float4*)(g_zn + (size_t)row * CZ + lane * 4) = o;
}

// ---------------- generic fp32 GEMM: C[Mx Nw] = A[M x 128] @ W[128 x Nw] ----
// 64x64 tile, 256 threads, 4x4 microtile, K chunked 2x64.
__global__ __launch_bounds__(256) void gemm128(const float* __restrict__ A,
                                               const float* __restrict__ W,
                                               float* __restrict__ C,
                                               int Nw, int do_sig)
{
    __shared__ float As[64 * 64];
    __shared__ float Bs[64 * 64];
    const int tid = threadIdx.x;
    const int m0  = blockIdx.x * 64;
    const int n0  = blockIdx.y * 64;
    const int tx  = tid & 15, ty = tid >> 4;
    float acc[4][4] = {};

    for (int kc = 0; kc < 2; ++kc) {
        #pragma unroll
        for (int it = 0; it < 4; ++it) {
            int idx = tid + it * 256;            // 64 rows x 16 float4
            int m = idx >> 4, kq = idx & 15;
            float4 a = *(const float4*)(A + (size_t)(m0 + m) * 128 + kc * 64 + kq * 4);
            *(float4*)&As[m * 64 + kq * 4] = a;
        }
        #pragma unroll
        for (int it = 0; it < 4; ++it) {
            int idx = tid + it * 256;            // 64 k-rows x 16 float4
            int k = idx >> 4, nq = idx & 15;
            float4 w = *(const float4*)(W + (size_t)(kc * 64 + k) * Nw + n0 + nq * 4);
            *(float4*)&Bs[k * 64 + nq * 4] = w;
        }
        __syncthreads();
        #pragma unroll 16
        for (int k = 0; k < 64; ++k) {
            float4 b = *(const float4*)&Bs[k * 64 + tx * 4];
            float a0 = As[(ty * 4 + 0) * 64 + k];
            float a1 = As[(ty * 4 + 1) * 64 + k];
            float a2 = As[(ty * 4 + 2) * 64 + k];
            float a3 = As[(ty * 4 + 3) * 64 + k];
            acc[0][0] += a0 * b.x; acc[0][1] += a0 * b.y; acc[0][2] += a0 * b.z; acc[0][3] += a0 * b.w;
            acc[1][0] += a1 * b.x; acc[1][1] += a1 * b.y; acc[1][2] += a1 * b.z; acc[1][3] += a1 * b.w;
            acc[2][0] += a2 * b.x; acc[2][1] += a2 * b.y; acc[2][2] += a2 * b.z; acc[2][3] += a2 * b.w;
            acc[3][0] += a3 * b.x; acc[3][1] += a3 * b.y; acc[3][2] += a3 * b.z; acc[3][3] += a3 * b.w;
        }
        __syncthreads();
    }
    #pragma unroll
    for (int r = 0; r < 4; ++r) {
        float4 v = make_float4(acc[r][0], acc[r][1], acc[r][2], acc[r][3]);
        if (do_sig) {
            v.x = 1.0f / (1.0f + __expf(-v.x));
            v.y = 1.0f / (1.0f + __expf(-v.y));
            v.z = 1.0f / (1.0f + __expf(-v.z));
            v.w = 1.0f / (1.0f + __expf(-v.w));
        }
        *(float4*)(C + (size_t)(m0 + ty * 4 + r) * Nw + n0 + tx * 4) = v;
    }
}

// ---------------- bias = zn @ W_b, stored as [h][row] ----------------
__global__ __launch_bounds__(256) void bias_kernel(const float* __restrict__ Wb)
{
    int row  = (blockIdx.x * blockDim.x + threadIdx.x) >> 5;
    int lane = threadIdx.x & 31;
    float4 v = *(const float4*)(g_zn + (size_t)row * CZ + lane * 4);
    const float4* W4 = (const float4*)Wb;           // W4[c] = (h0..h3) of row c
    float4 acc = make_float4(0.f, 0.f, 0.f, 0.f);
    float vv[4] = {v.x, v.y, v.z, v.w};
    #pragma unroll
    for (int t = 0; t < 4; ++t) {
        float4 w = W4[lane * 4 + t];
        acc.x += vv[t] * w.x; acc.y += vv[t] * w.y;
        acc.z += vv[t] * w.z; acc.w += vv[t] * w.w;
    }
    #pragma unroll
    for (int m = 16; m; m >>= 1) {
        acc.x += __shfl_xor_sync(0xffffffffu, acc.x, m);
        acc.y += __shfl_xor_sync(0xffffffffu, acc.y, m);
        acc.z += __shfl_xor_sync(0xffffffffu, acc.z, m);
        acc.w += __shfl_xor_sync(0xffffffffu, acc.w, m);
    }
    if (lane == 0) {
        g_bias[(size_t)0 * NROWS + row] = acc.x;
        g_bias[(size_t)1 * NROWS + row] = acc.y;
        g_bias[(size_t)2 * NROWS + row] = acc.z;
        g_bias[(size_t)3 * NROWS + row] = acc.w;
    }
}

// ---------------- attention: one CTA per (i, h, 64-row j-tile) --------------
// smem floats: Qs 32x68, Ks 32x260, Vs 256x36, Ps 64x260
#define QS_STRIDE 68
#define KS_STRIDE 260
#define VS_STRIDE 36
#define PS_STRIDE 260
#define ATTN_SMEM ((32*QS_STRIDE + 32*KS_STRIDE + 256*VS_STRIDE + 64*PS_STRIDE) * 4)

__global__ __launch_bounds__(256) void attn_kernel()
{
    extern __shared__ float sm[];
    float* Qs = sm;
    float* Ks = Qs + 32 * QS_STRIDE;
    float* Vs = Ks + 32 * KS_STRIDE;
    float* Ps = Vs + 256 * VS_STRIDE;

    const int tid = threadIdx.x;
    const int jt  = blockIdx.x;     // 0..3  (64-row tile of j)
    const int h   = blockIdx.y;     // 0..3
    const int i   = blockIdx.z;     // 0..255

    const float* base = g_qkv + (size_t)i * NSEQ * 384 + h * 32;

    // stage Q tile (transposed [c][j])
    #pragma unroll
    for (int it = 0; it < 2; ++it) {
        int idx = tid + it * 256;                 // 64 rows x 8 float4
        int jj = idx >> 3, cq = idx & 7;
        float4 v = *(const float4*)(base + (size_t)(jt * 64 + jj) * 384 + cq * 4);
        Qs[(cq * 4 + 0) * QS_STRIDE + jj] = v.x;
        Qs[(cq * 4 + 1) * QS_STRIDE + jj] = v.y;
        Qs[(cq * 4 + 2) * QS_STRIDE + jj] = v.z;
        Qs[(cq * 4 + 3) * QS_STRIDE + jj] = v.w;
    }
    // stage K (transposed [c][k]) and V ([k][c])
    #pragma unroll
    for (int it = 0; it < 8; ++it) {
        int idx = tid + it * 256;                 // 256 rows x 8 float4
        int k = idx >> 3, cq = idx & 7;
        float4 v = *(const float4*)(base + 128 + (size_t)k * 384 + cq * 4);
        Ks[(cq * 4 + 0) * KS_STRIDE + k] = v.x;
        Ks[(cq * 4 + 1) * KS_STRIDE + k] = v.y;
        Ks[(cq * 4 + 2) * KS_STRIDE + k] = v.z;
        Ks[(cq * 4 + 3) * KS_STRIDE + k] = v.w;
        float4 w = *(const float4*)(base + 256 + (size_t)k * 384 + cq * 4);
        *(float4*)&Vs[k * VS_STRIDE + cq * 4] = w;
    }
    __syncthreads();

    // ---- phase A: S = Q K^T (64x256), thread = 4 rows x 16 cols ----
    const int tx = tid & 15, ty = tid >> 4;
    float acc[4][16];
    #pragma unroll
    for (int r = 0; r < 4; ++r)
        #pragma unroll
        for (int q = 0; q < 16; ++q) acc[r][q] = 0.0f;

    #pragma unroll 8
    for (int c = 0; c < 32; ++c) {
        float4 a  = *(const float4*)&Qs[c * QS_STRIDE + ty * 4];
        float4 b0 = *(const float4*)&Ks[c * KS_STRIDE + tx * 16 + 0];
        float4 b1 = *(const float4*)&Ks[c * KS_STRIDE + tx * 16 + 4];
        float4 b2 = *(const float4*)&Ks[c * KS_STRIDE + tx * 16 + 8];
        float4 b3 = *(const float4*)&Ks[c * KS_STRIDE + tx * 16 + 12];
        float ar[4] = {a.x, a.y, a.z, a.w};
        float bv[16] = {b0.x,b0.y,b0.z,b0.w, b1.x,b1.y,b1.z,b1.w,
                        b2.x,b2.y,b2.z,b2.w, b3.x,b3.y,b3.z,b3.w};
        #pragma unroll
        for (int r = 0; r < 4; ++r)
            #pragma unroll
            for (int q = 0; q < 16; ++q) acc[r][q] += ar[r] * bv[q];
    }

    // ---- softmax over k (row shared by 16 consecutive lanes) ----
    const float scale = 0.17677669529663687f;   // 1/sqrt(32)
    #pragma unroll
    for (int r = 0; r < 4; ++r) {
        int jg = jt * 64 + ty * 4 + r;
        const float4* bp = (const float4*)(g_bias + (size_t)h * NROWS + (size_t)jg * NSEQ + tx * 16);
        float4 B0 = bp[0], B1 = bp[1], B2 = bp[2], B3 = bp[3];
        float bb[16] = {B0.x,B0.y,B0.z,B0.w, B1.x,B1.y,B1.z,B1.w,
                        B2.x,B2.y,B2.z,B2.w, B3.x,B3.y,B3.z,B3.w};
        float s[16];
        float mx = -1e30f;
        #pragma unroll
        for (int q = 0; q < 16; ++q) {
            s[q] = acc[r][q] * scale + bb[q];
            mx = fmaxf(mx, s[q]);
        }
        #pragma unroll
        for (int m = 8; m; m >>= 1) mx = fmaxf(mx, __shfl_xor_sync(0xffffffffu, mx, m));
        float sum = 0.0f;
        #pragma unroll
        for (int q = 0; q < 16; ++q) { s[q] = __expf(s[q] - mx); sum += s[q]; }
        #pragma unroll
        for (int m = 8; m; m >>= 1) sum += __shfl_xor_sync(0xffffffffu, sum, m);
        float inv = 1.0f / sum;
        #pragma unroll
        for (int q = 0; q < 16; ++q) s[q] *= inv;
        float* pr = &Ps[(ty * 4 + r) * PS_STRIDE + tx * 16];
        *(float4*)(pr + 0)  = make_float4(s[0],  s[1],  s[2],  s[3]);
        *(float4*)(pr + 4)  = make_float4(s[4],  s[5],  s[6],  s[7]);
        *(float4*)(pr + 8)  = make_float4(s[8],  s[9],  s[10], s[11]);
        *(float4*)(pr + 12) = make_float4(s[12], s[13], s[14], s[15]);
    }
    __syncthreads();

    // ---- phase B: O = P V (64x32), thread = 4 rows x 2 cols ----
    const int txB = tid & 15, tyB = tid >> 4;   // c0 = txB*2, j0 = tyB*4
    float o[4][2] = {};
    #pragma unroll 4
    for (int k = 0; k < 256; k += 4) {
        float4 p[4];
        #pragma unroll
        for (int r = 0; r < 4; ++r)
            p[r] = *(const float4*)&Ps[(tyB * 4 + r) * PS_STRIDE + k];
        float2 v[4];
        #pragma unroll
        for (int kk = 0; kk < 4; ++kk)
            v[kk] = *(const float2*)&Vs[(k + kk) * VS_STRIDE + txB * 2];
        #pragma unroll
        for (int r = 0; r < 4; ++r) {
            o[r][0] += p[r].x * v[0].x + p[r].y * v[1].x + p[r].z * v[2].x + p[r].w * v[3].x;
            o[r][1] += p[r].x * v[0].y + p[r].y * v[1].y + p[r].z * v[2].y + p[r].w * v[3].y;
        }
    }
    // gate + store
    #pragma unroll
    for (int r = 0; r < 4; ++r) {
        int jg = jt * 64 + tyB * 4 + r;
        size_t row = (size_t)i * NSEQ + jg;
        float2 gt = *(const float2*)(g_gate + row * 128 + h * 32 + txB * 2);
        float2 outv;
        outv.x = o[r][0] * gt.x;
        outv.y = o[r][1] * gt.y;
        *(float2*)(g_go + row * 128 + h * 32 + txB * 2) = outv;
    }
}

// ---------------- launch ----------------
extern "C" void kernel_launch(void* const* d_in, const int* in_sizes, int n_in,
                              void* d_out, int out_size)
{
    const float* z    = (const float*)d_in[0];
    const float* ln_g = (const float*)d_in[1];
    const float* ln_b = (const float*)d_in[2];
    const float* Wqkv = (const float*)d_in[3];
    const float* Wb   = (const float*)d_in[4];
    const float* Wg   = (const float*)d_in[5];
    const float* Wo   = (const float*)d_in[6];
    float* out = (float*)d_out;

    cudaFuncSetAttribute(attn_kernel, cudaFuncAttributeMaxDynamicSharedMemorySize, ATTN_SMEM);

    void *pzn, *pqkv, *pgate, *pgo;
    cudaGetSymbolAddress(&pzn,   g_zn);
    cudaGetSymbolAddress(&pqkv,  g_qkv);
    cudaGetSymbolAddress(&pgate, g_gate);
    cudaGetSymbolAddress(&pgo,   g_go);

    ln_kernel<<<NROWS / 8, 256>>>(z, ln_g, ln_b);
    gemm128<<<dim3(NROWS / 64, 6), 256>>>((const float*)pzn, Wqkv, (float*)pqkv, 384, 0);
    gemm128<<<dim3(NROWS / 64, 2), 256>>>((const float*)pzn, Wg, (float*)pgate, 128, 1);
    bias_kernel<<<NROWS / 8, 256>>>(Wb);
    attn_kernel<<<dim3(4, 4, 256), 256, ATTN_SMEM>>>();
    gemm128<<<dim3(NROWS / 64, 2), 256>>>((const float*)pgo, Wo, out, 128, 0);
}

// round 6
// speedup vs baseline: 1.0993x; 1.0993x over previous
#include <cuda_runtime.h>
#include <cuda_bf16.h>
#include <cstdint>
#include <math.h>

typedef __nv_bfloat16 bf16;

#define NSEQ 256
#define CZ   128
#define NHEAD 4
#define CHEAD 32
#define NROWS (NSEQ*NSEQ)   // 65536

// ---------------- scratch (static __device__, no allocation) ----------------
__device__ bf16  g_zn_h[(size_t)NROWS * CZ];        // hi(LN(z))      16.8 MB
__device__ bf16  g_zn_l[(size_t)NROWS * CZ];        // lo(LN(z))      16.8 MB
__device__ float g_qkv [(size_t)NROWS * 3 * CZ];    // q|k|v          100 MB
__device__ float g_gate[(size_t)NROWS * CZ];        // sigmoid(z@Wg)  33.5 MB
__device__ float g_bias[(size_t)NHEAD * NROWS];     // [h][row]       1 MB
__device__ bf16  g_go_h[(size_t)NROWS * CZ];        // hi(gate*o)     16.8 MB
__device__ bf16  g_go_l[(size_t)NROWS * CZ];        // lo(gate*o)     16.8 MB
// split weights
__device__ bf16 g_wqkv_h[128 * 384], g_wqkv_l[128 * 384];
__device__ bf16 g_wg_h  [128 * 128], g_wg_l  [128 * 128];
__device__ bf16 g_wo_h  [128 * 128], g_wo_l  [128 * 128];

// ---------------- LayerNorm + bf16 split: one warp per 128-float row --------
__global__ __launch_bounds__(256) void ln_kernel(const float* __restrict__ z,
                                                 const float* __restrict__ gam,
                                                 const float* __restrict__ bet)
{
    int row  = (blockIdx.x * blockDim.x + threadIdx.x) >> 5;
    int lane = threadIdx.x & 31;
    float4 v = *(const float4*)(z + (size_t)row * CZ + lane * 4);
    float s  = v.x + v.y + v.z + v.w;
    float ss = v.x*v.x + v.y*v.y + v.z*v.z + v.w*v.w;
    #pragma unroll
    for (int m = 16; m; m >>= 1) {
        s  += __shfl_xor_sync(0xffffffffu, s,  m);
        ss += __shfl_xor_sync(0xffffffffu, ss, m);
    }
    float mu   = s * (1.0f / CZ);
    float var  = ss * (1.0f / CZ) - mu * mu;
    float rstd = rsqrtf(var + 1e-5f);
    float4 gg = *(const float4*)(gam + lane * 4);
    float4 bb = *(const float4*)(bet + lane * 4);
    float o[4];
    o[0] = (v.x - mu) * rstd * gg.x + bb.x;
    o[1] = (v.y - mu) * rstd * gg.y + bb.y;
    o[2] = (v.z - mu) * rstd * gg.z + bb.z;
    o[3] = (v.w - mu) * rstd * gg.w + bb.w;
    bf16 h[4], l[4];
    #pragma unroll
    for (int t = 0; t < 4; ++t) {
        h[t] = __float2bfloat16(o[t]);
        l[t] = __float2bfloat16(o[t] - __bfloat162float(h[t]));
    }
    *(uint2*)(g_zn_h + (size_t)row * CZ + lane * 4) = *(uint2*)h;
    *(uint2*)(g_zn_l + (size_t)row * CZ + lane * 4) = *(uint2*)l;
}

// ---------------- split the weights into hi/lo bf16 ----------------
__global__ __launch_bounds__(256) void cvt_w(const float* __restrict__ Wqkv,
                                             const float* __restrict__ Wg,
                                             const float* __restrict__ Wo)
{
    int i = blockIdx.x * 256 + threadIdx.x;   // 0..81919
    float x;
    bf16 *H, *L;
    int off;
    if (i < 49152)      { x = Wqkv[i];        H = g_wqkv_h; L = g_wqkv_l; off = i; }
    else if (i < 65536) { x = Wg[i - 49152];  H = g_wg_h;   L = g_wg_l;   off = i - 49152; }
    else                { x = Wo[i - 65536];  H = g_wo_h;   L = g_wo_l;   off = i - 65536; }
    bf16 h = __float2bfloat16(x);
    H[off] = h;
    L[off] = __float2bfloat16(x - __bfloat162float(h));
}

// ---------------- tensor-core GEMM: C[M x Nw] = (Ah+Al)[M x 128] @ (Bh+Bl)[128 x Nw]
// CTA 128x128, 256 thr (8 warps 4x2), warp tile 32x64, K chunks of 32.
// bf16-split: D += Ah*Bh + Ah*Bl + Al*Bh  (fp32 accumulate).
#define AS_STR 40   // bf16 stride -> conflict-free frag loads
#define BS_STR 40

#define MMA16816(d, a, b0v, b1v)                                             \
  asm volatile("mma.sync.aligned.m16n8k16.row.col.f32.bf16.bf16.f32 "        \
    "{%0,%1,%2,%3}, {%4,%5,%6,%7}, {%8,%9}, {%0,%1,%2,%3};"                  \
    : "+f"(d[0]), "+f"(d[1]), "+f"(d[2]), "+f"(d[3])                         \
    : "r"(a[0]), "r"(a[1]), "r"(a[2]), "r"(a[3]), "r"(b0v), "r"(b1v))

__global__ __launch_bounds__(256) void mma_gemm(
    const bf16* __restrict__ Ah, const bf16* __restrict__ Al,
    const bf16* __restrict__ Bh, const bf16* __restrict__ Bl,
    float* __restrict__ C, int Nw, int do_sig)
{
    __shared__ bf16 Ash[128 * AS_STR], Asl[128 * AS_STR];
    __shared__ bf16 Bsh[128 * BS_STR], Bsl[128 * BS_STR];
    const int tid  = threadIdx.x;
    const int wid  = tid >> 5, lane = tid & 31;
    const int m0   = blockIdx.x * 128;
    const int n0   = blockIdx.y * 128;
    const int wm   = (wid & 3) * 32;
    const int wn   = (wid >> 2) * 64;
    const int lr   = lane >> 2;          // 0..7
    const int lc   = lane & 3;           // 0..3

    float acc[2][8][4];
    #pragma unroll
    for (int mt = 0; mt < 2; ++mt)
        #pragma unroll
        for (int nt = 0; nt < 8; ++nt)
            #pragma unroll
            for (int e = 0; e < 4; ++e) acc[mt][nt][e] = 0.0f;

    for (int kc = 0; kc < 4; ++kc) {
        // ---- stage A (rows 128 x k 32), row-major, pad 40 ----
        #pragma unroll
        for (int it = 0; it < 2; ++it) {
            int idx = tid + it * 256;            // 512 uint4 per array
            int row = idx >> 2, kq = idx & 3;
            uint4 vh = *(const uint4*)(Ah + (size_t)(m0 + row) * 128 + kc * 32 + kq * 8);
            *(uint4*)&Ash[row * AS_STR + kq * 8] = vh;
            uint4 vl = *(const uint4*)(Al + (size_t)(m0 + row) * 128 + kc * 32 + kq * 8);
            *(uint4*)&Asl[row * AS_STR + kq * 8] = vl;
        }
        // ---- stage B transposed: Bs[n][k], k XOR-swizzled by 2*(n>>3) ----
        #pragma unroll
        for (int it = 0; it < 2; ++it) {
            int idx = tid + it * 256;            // 512 uint4 per array
            int k = idx >> 4, nq = idx & 15;     // k 0..31, nq 0..15
            int sw = k ^ (2 * nq);
            uint4 vh = *(const uint4*)(Bh + (size_t)(kc * 32 + k) * Nw + n0 + nq * 8);
            uint4 vl = *(const uint4*)(Bl + (size_t)(kc * 32 + k) * Nw + n0 + nq * 8);
            bf16 th[8], tl[8];
            *(uint4*)th = vh; *(uint4*)tl = vl;
            #pragma unroll
            for (int e = 0; e < 8; ++e) {
                Bsh[(nq * 8 + e) * BS_STR + sw] = th[e];
                Bsl[(nq * 8 + e) * BS_STR + sw] = tl[e];
            }
        }
        __syncthreads();

        #pragma unroll
        for (int kh = 0; kh < 2; ++kh) {
            const int kb = kh * 16;
            uint32_t afh[2][4], afl[2][4];
            #pragma unroll
            for (int mt = 0; mt < 2; ++mt) {
                int r = wm + mt * 16 + lr;
                int kcol = kb + lc * 2;
                afh[mt][0] = *(const uint32_t*)&Ash[ r      * AS_STR + kcol];
                afh[mt][1] = *(const uint32_t*)&Ash[(r + 8) * AS_STR + kcol];
                afh[mt][2] = *(const uint32_t*)&Ash[ r      * AS_STR + kcol + 8];
                afh[mt][3] = *(const uint32_t*)&Ash[(r + 8) * AS_STR + kcol + 8];
                afl[mt][0] = *(const uint32_t*)&Asl[ r      * AS_STR + kcol];
                afl[mt][1] = *(const uint32_t*)&Asl[(r + 8) * AS_STR + kcol];
                afl[mt][2] = *(const uint32_t*)&Asl[ r      * AS_STR + kcol + 8];
                afl[mt][3] = *(const uint32_t*)&Asl[(r + 8) * AS_STR + kcol + 8];
            }
            #pragma unroll
            for (int nt = 0; nt < 8; ++nt) {
                int n   = wn + nt * 8 + lr;
                int s   = 2 * ((n >> 3) & 15);
                int c0  = kb + lc * 2;
                uint32_t bh0 = *(const uint32_t*)&Bsh[n * BS_STR + ( c0      ^ s)];
                uint32_t bh1 = *(const uint32_t*)&Bsh[n * BS_STR + ((c0 + 8) ^ s)];
                uint32_t bl0 = *(const uint32_t*)&Bsl[n * BS_STR + ( c0      ^ s)];
                uint32_t bl1 = *(const uint32_t*)&Bsl[n * BS_STR + ((c0 + 8) ^ s)];
                #pragma unroll
                for (int mt = 0; mt < 2; ++mt) {
                    MMA16816(acc[mt][nt], afh[mt], bh0, bh1);
                    MMA16816(acc[mt][nt], afh[mt], bl0, bl1);
                    MMA16816(acc[mt][nt], afl[mt], bh0, bh1);
                }
            }
        }
        __syncthreads();
    }
    // ---- epilogue ----
    #pragma unroll
    for (int mt = 0; mt < 2; ++mt) {
        size_t r = (size_t)(m0 + wm + mt * 16 + lr);
        #pragma unroll
        for (int nt = 0; nt < 8; ++nt) {
            int n = n0 + wn + nt * 8 + lc * 2;
            float2 v0 = make_float2(acc[mt][nt][0], acc[mt][nt][1]);
            float2 v1 = make_float2(acc[mt][nt][2], acc[mt][nt][3]);
            if (do_sig) {
                v0.x = 1.0f / (1.0f + __expf(-v0.x));
                v0.y = 1.0f / (1.0f + __expf(-v0.y));
                v1.x = 1.0f / (1.0f + __expf(-v1.x));
                v1.y = 1.0f / (1.0f + __expf(-v1.y));
            }
            *(float2*)(C + r * Nw + n)       = v0;
            *(float2*)(C + (r + 8) * Nw + n) = v1;
        }
    }
}

// ---------------- bias = zn @ W_b, stored as [h][row] ----------------
__global__ __launch_bounds__(256) void bias_kernel(const float* __restrict__ Wb)
{
    int row  = (blockIdx.x * blockDim.x + threadIdx.x) >> 5;
    int lane = threadIdx.x & 31;
    uint2 uh = *(const uint2*)(g_zn_h + (size_t)row * CZ + lane * 4);
    uint2 ul = *(const uint2*)(g_zn_l + (size_t)row * CZ + lane * 4);
    bf16 hh[4], ll[4];
    *(uint2*)hh = uh; *(uint2*)ll = ul;
    float vv[4];
    #pragma unroll
    for (int t = 0; t < 4; ++t)
        vv[t] = __bfloat162float(hh[t]) + __bfloat162float(ll[t]);
    const float4* W4 = (const float4*)Wb;           // W4[c] = (h0..h3) of row c
    float4 acc = make_float4(0.f, 0.f, 0.f, 0.f);
    #pragma unroll
    for (int t = 0; t < 4; ++t) {
        float4 w = W4[lane * 4 + t];
        acc.x += vv[t] * w.x; acc.y += vv[t] * w.y;
        acc.z += vv[t] * w.z; acc.w += vv[t] * w.w;
    }
    #pragma unroll
    for (int m = 16; m; m >>= 1) {
        acc.x += __shfl_xor_sync(0xffffffffu, acc.x, m);
        acc.y += __shfl_xor_sync(0xffffffffu, acc.y, m);
        acc.z += __shfl_xor_sync(0xffffffffu, acc.z, m);
        acc.w += __shfl_xor_sync(0xffffffffu, acc.w, m);
    }
    if (lane == 0) {
        g_bias[(size_t)0 * NROWS + row] = acc.x;
        g_bias[(size_t)1 * NROWS + row] = acc.y;
        g_bias[(size_t)2 * NROWS + row] = acc.z;
        g_bias[(size_t)3 * NROWS + row] = acc.w;
    }
}

// ---------------- attention: one CTA per (i, h, 64-row j-tile) --------------
#define QS_STRIDE 68
#define KS_STRIDE 260
#define VS_STRIDE 36
#define PS_STRIDE 260
#define ATTN_SMEM ((32*QS_STRIDE + 32*KS_STRIDE + 256*VS_STRIDE + 64*PS_STRIDE) * 4)

__global__ __launch_bounds__(256) void attn_kernel()
{
    extern __shared__ float sm[];
    float* Qs = sm;
    float* Ks = Qs + 32 * QS_STRIDE;
    float* Vs = Ks + 32 * KS_STRIDE;
    float* Ps = Vs + 256 * VS_STRIDE;

    const int tid = threadIdx.x;
    const int jt  = blockIdx.x;     // 0..3
    const int h   = blockIdx.y;     // 0..3
    const int i   = blockIdx.z;     // 0..255

    const float* base = g_qkv + (size_t)i * NSEQ * 384 + h * 32;

    #pragma unroll
    for (int it = 0; it < 2; ++it) {
        int idx = tid + it * 256;
        int jj = idx >> 3, cq = idx & 7;
        float4 v = *(const float4*)(base + (size_t)(jt * 64 + jj) * 384 + cq * 4);
        Qs[(cq * 4 + 0) * QS_STRIDE + jj] = v.x;
        Qs[(cq * 4 + 1) * QS_STRIDE + jj] = v.y;
        Qs[(cq * 4 + 2) * QS_STRIDE + jj] = v.z;
        Qs[(cq * 4 + 3) * QS_STRIDE + jj] = v.w;
    }
    #pragma unroll
    for (int it = 0; it < 8; ++it) {
        int idx = tid + it * 256;
        int k = idx >> 3, cq = idx & 7;
        float4 v = *(const float4*)(base + 128 + (size_t)k * 384 + cq * 4);
        Ks[(cq * 4 + 0) * KS_STRIDE + k] = v.x;
        Ks[(cq * 4 + 1) * KS_STRIDE + k] = v.y;
        Ks[(cq * 4 + 2) * KS_STRIDE + k] = v.z;
        Ks[(cq * 4 + 3) * KS_STRIDE + k] = v.w;
        float4 w = *(const float4*)(base + 256 + (size_t)k * 384 + cq * 4);
        *(float4*)&Vs[k * VS_STRIDE + cq * 4] = w;
    }
    __syncthreads();

    const int tx = tid & 15, ty = tid >> 4;
    float acc[4][16];
    #pragma unroll
    for (int r = 0; r < 4; ++r)
        #pragma unroll
        for (int q = 0; q < 16; ++q) acc[r][q] = 0.0f;

    #pragma unroll 8
    for (int c = 0; c < 32; ++c) {
        float4 a  = *(const float4*)&Qs[c * QS_STRIDE + ty * 4];
        float4 b0 = *(const float4*)&Ks[c * KS_STRIDE + tx * 16 + 0];
        float4 b1 = *(const float4*)&Ks[c * KS_STRIDE + tx * 16 + 4];
        float4 b2 = *(const float4*)&Ks[c * KS_STRIDE + tx * 16 + 8];
        float4 b3 = *(const float4*)&Ks[c * KS_STRIDE + tx * 16 + 12];
        float ar[4] = {a.x, a.y, a.z, a.w};
        float bv[16] = {b0.x,b0.y,b0.z,b0.w, b1.x,b1.y,b1.z,b1.w,
                        b2.x,b2.y,b2.z,b2.w, b3.x,b3.y,b3.z,b3.w};
        #pragma unroll
        for (int r = 0; r < 4; ++r)
            #pragma unroll
            for (int q = 0; q < 16; ++q) acc[r][q] += ar[r] * bv[q];
    }

    const float scale = 0.17677669529663687f;   // 1/sqrt(32)
    #pragma unroll
    for (int r = 0; r < 4; ++r) {
        int jg = jt * 64 + ty * 4 + r;
        const float4* bp = (const float4*)(g_bias + (size_t)h * NROWS + (size_t)jg * NSEQ + tx * 16);
        float4 B0 = bp[0], B1 = bp[1], B2 = bp[2], B3 = bp[3];
        float bb[16] = {B0.x,B0.y,B0.z,B0.w, B1.x,B1.y,B1.z,B1.w,
                        B2.x,B2.y,B2.z,B2.w, B3.x,B3.y,B3.z,B3.w};
        float s[16];
        float mx = -1e30f;
        #pragma unroll
        for (int q = 0; q < 16; ++q) {
            s[q] = acc[r][q] * scale + bb[q];
            mx = fmaxf(mx, s[q]);
        }
        #pragma unroll
        for (int m = 8; m; m >>= 1) mx = fmaxf(mx, __shfl_xor_sync(0xffffffffu, mx, m));
        float sum = 0.0f;
        #pragma unroll
        for (int q = 0; q < 16; ++q) { s[q] = __expf(s[q] - mx); sum += s[q]; }
        #pragma unroll
        for (int m = 8; m; m >>= 1) sum += __shfl_xor_sync(0xffffffffu, sum, m);
        float inv = 1.0f / sum;
        #pragma unroll
        for (int q = 0; q < 16; ++q) s[q] *= inv;
        float* pr = &Ps[(ty * 4 + r) * PS_STRIDE + tx * 16];
        *(float4*)(pr + 0)  = make_float4(s[0],  s[1],  s[2],  s[3]);
        *(float4*)(pr + 4)  = make_float4(s[4],  s[5],  s[6],  s[7]);
        *(float4*)(pr + 8)  = make_float4(s[8],  s[9],  s[10], s[11]);
        *(float4*)(pr + 12) = make_float4(s[12], s[13], s[14], s[15]);
    }
    __syncthreads();

    const int txB = tid & 15, tyB = tid >> 4;
    float o[4][2] = {};
    #pragma unroll 4
    for (int k = 0; k < 256; k += 4) {
        float4 p[4];
        #pragma unroll
        for (int r = 0; r < 4; ++r)
            p[r] = *(const float4*)&Ps[(tyB * 4 + r) * PS_STRIDE + k];
        float2 v[4];
        #pragma unroll
        for (int kk = 0; kk < 4; ++kk)
            v[kk] = *(const float2*)&Vs[(k + kk) * VS_STRIDE + txB * 2];
        #pragma unroll
        for (int r = 0; r < 4; ++r) {
            o[r][0] += p[r].x * v[0].x + p[r].y * v[1].x + p[r].z * v[2].x + p[r].w * v[3].x;
            o[r][1] += p[r].x * v[0].y + p[r].y * v[1].y + p[r].z * v[2].y + p[r].w * v[3].y;
        }
    }
    // gate + bf16 hi/lo split store (feeds output tensor-core GEMM)
    #pragma unroll
    for (int r = 0; r < 4; ++r) {
        int jg = jt * 64 + tyB * 4 + r;
        size_t row = (size_t)i * NSEQ + jg;
        float2 gt = *(const float2*)(g_gate + row * 128 + h * 32 + txB * 2);
        float x0 = o[r][0] * gt.x;
        float x1 = o[r][1] * gt.y;
        bf16 h0 = __float2bfloat16(x0);
        bf16 h1 = __float2bfloat16(x1);
        bf16 l0 = __float2bfloat16(x0 - __bfloat162float(h0));
        bf16 l1 = __float2bfloat16(x1 - __bfloat162float(h1));
        __nv_bfloat162 ph; ph.x = h0; ph.y = h1;
        __nv_bfloat162 pl; pl.x = l0; pl.y = l1;
        *(__nv_bfloat162*)(g_go_h + row * 128 + h * 32 + txB * 2) = ph;
        *(__nv_bfloat162*)(g_go_l + row * 128 + h * 32 + txB * 2) = pl;
    }
}

// ---------------- launch ----------------
extern "C" void kernel_launch(void* const* d_in, const int* in_sizes, int n_in,
                              void* d_out, int out_size)
{
    const float* z    = (const float*)d_in[0];
    const float* ln_g = (const float*)d_in[1];
    const float* ln_b = (const float*)d_in[2];
    const float* Wqkv = (const float*)d_in[3];
    const float* Wb   = (const float*)d_in[4];
    const float* Wg   = (const float*)d_in[5];
    const float* Wo   = (const float*)d_in[6];
    float* out = (float*)d_out;

    cudaFuncSetAttribute(attn_kernel, cudaFuncAttributeMaxDynamicSharedMemorySize, ATTN_SMEM);

    void *pznh, *pznl, *pqkv, *pgate, *pgoh, *pgol;
    void *pwqh, *pwql, *pwgh, *pwgl, *pwoh, *pwol;
    cudaGetSymbolAddress(&pznh, g_zn_h);
    cudaGetSymbolAddress(&pznl, g_zn_l);
    cudaGetSymbolAddress(&pqkv, g_qkv);
    cudaGetSymbolAddress(&pgate, g_gate);
    cudaGetSymbolAddress(&pgoh, g_go_h);
    cudaGetSymbolAddress(&pgol, g_go_l);
    cudaGetSymbolAddress(&pwqh, g_wqkv_h);
    cudaGetSymbolAddress(&pwql, g_wqkv_l);
    cudaGetSymbolAddress(&pwgh, g_wg_h);
    cudaGetSymbolAddress(&pwgl, g_wg_l);
    cudaGetSymbolAddress(&pwoh, g_wo_h);
    cudaGetSymbolAddress(&pwol, g_wo_l);

    ln_kernel<<<NROWS / 8, 256>>>(z, ln_g, ln_b);
    cvt_w<<<320, 256>>>(Wqkv, Wg, Wo);
    // qkv = zn @ Wqkv  (65536 x 384)
    mma_gemm<<<dim3(NROWS / 128, 3), 256>>>((const bf16*)pznh, (const bf16*)pznl,
                                            (const bf16*)pwqh, (const bf16*)pwql,
                                            (float*)pqkv, 384, 0);
    // gate = sigmoid(zn @ Wg)  (65536 x 128)
    mma_gemm<<<dim3(NROWS / 128, 1), 256>>>((const bf16*)pznh, (const bf16*)pznl,
                                            (const bf16*)pwgh, (const bf16*)pwgl,
                                            (float*)pgate, 128, 1);
    bias_kernel<<<NROWS / 8, 256>>>(Wb);
    attn_kernel<<<dim3(4, 4, 256), 256, ATTN_SMEM>>>();
    // out = (gate*o) @ Wo  (65536 x 128)
    mma_gemm<<<dim3(NROWS / 128, 1), 256>>>((const bf16*)pgoh, (const bf16*)pgol,
                                            (const bf16*)pwoh, (const bf16*)pwol,
                                            out, 128, 0);
}

// round 7
// speedup vs baseline: 1.4024x; 1.2758x over previous
#include <cuda_runtime.h>
#include <cuda_bf16.h>
#include <cstdint>
#include <math.h>

typedef __nv_bfloat16 bf16;

#define NSEQ 256
#define CZ   128
#define NHEAD 4
#define CHEAD 32
#define NROWS (NSEQ*NSEQ)   // 65536

// ---------------- scratch (static __device__, no allocation) ----------------
__device__ bf16  g_zn_h[(size_t)NROWS * CZ];        // hi(LN(z))      16.8 MB
__device__ bf16  g_zn_l[(size_t)NROWS * CZ];        // lo(LN(z))      16.8 MB
__device__ float g_qkv [(size_t)NROWS * 3 * CZ];    // q|k|v          100 MB
__device__ float g_gate[(size_t)NROWS * CZ];        // sigmoid(z@Wg)  33.5 MB
__device__ float g_bias[(size_t)NHEAD * NROWS];     // [h][row]       1 MB
__device__ bf16  g_go_h[(size_t)NROWS * CZ];        // hi(gate*o)     16.8 MB
__device__ bf16  g_go_l[(size_t)NROWS * CZ];        // lo(gate*o)     16.8 MB
// split weights
__device__ bf16 g_wqkv_h[128 * 384], g_wqkv_l[128 * 384];
__device__ bf16 g_wg_h  [128 * 128], g_wg_l  [128 * 128];
__device__ bf16 g_wo_h  [128 * 128], g_wo_l  [128 * 128];

// ---------------- LayerNorm + bf16 split + fused pair-bias ----------------
// one warp per 128-float row; bias = zn @ W_b computed from registers.
__global__ __launch_bounds__(256) void ln_kernel(const float* __restrict__ z,
                                                 const float* __restrict__ gam,
                                                 const float* __restrict__ bet,
                                                 const float* __restrict__ Wb)
{
    int row  = (blockIdx.x * blockDim.x + threadIdx.x) >> 5;
    int lane = threadIdx.x & 31;
    float4 v = *(const float4*)(z + (size_t)row * CZ + lane * 4);
    float s  = v.x + v.y + v.z + v.w;
    float ss = v.x*v.x + v.y*v.y + v.z*v.z + v.w*v.w;
    #pragma unroll
    for (int m = 16; m; m >>= 1) {
        s  += __shfl_xor_sync(0xffffffffu, s,  m);
        ss += __shfl_xor_sync(0xffffffffu, ss, m);
    }
    float mu   = s * (1.0f / CZ);
    float var  = ss * (1.0f / CZ) - mu * mu;
    float rstd = rsqrtf(var + 1e-5f);
    float4 gg = *(const float4*)(gam + lane * 4);
    float4 bb = *(const float4*)(bet + lane * 4);
    float o[4];
    o[0] = (v.x - mu) * rstd * gg.x + bb.x;
    o[1] = (v.y - mu) * rstd * gg.y + bb.y;
    o[2] = (v.z - mu) * rstd * gg.z + bb.z;
    o[3] = (v.w - mu) * rstd * gg.w + bb.w;
    bf16 h[4], l[4];
    #pragma unroll
    for (int t = 0; t < 4; ++t) {
        h[t] = __float2bfloat16(o[t]);
        l[t] = __float2bfloat16(o[t] - __bfloat162float(h[t]));
    }
    *(uint2*)(g_zn_h + (size_t)row * CZ + lane * 4) = *(uint2*)h;
    *(uint2*)(g_zn_l + (size_t)row * CZ + lane * 4) = *(uint2*)l;

    // fused bias: acc[h'] = sum_c zn[c] * Wb[c][h']
    const float4* W4 = (const float4*)Wb;           // W4[c] = (h0..h3) of row c
    float4 acc = make_float4(0.f, 0.f, 0.f, 0.f);
    #pragma unroll
    for (int t = 0; t < 4; ++t) {
        float4 w = W4[lane * 4 + t];
        acc.x += o[t] * w.x; acc.y += o[t] * w.y;
        acc.z += o[t] * w.z; acc.w += o[t] * w.w;
    }
    #pragma unroll
    for (int m = 16; m; m >>= 1) {
        acc.x += __shfl_xor_sync(0xffffffffu, acc.x, m);
        acc.y += __shfl_xor_sync(0xffffffffu, acc.y, m);
        acc.z += __shfl_xor_sync(0xffffffffu, acc.z, m);
        acc.w += __shfl_xor_sync(0xffffffffu, acc.w, m);
    }
    if (lane == 0) {
        g_bias[(size_t)0 * NROWS + row] = acc.x;
        g_bias[(size_t)1 * NROWS + row] = acc.y;
        g_bias[(size_t)2 * NROWS + row] = acc.z;
        g_bias[(size_t)3 * NROWS + row] = acc.w;
    }
}

// ---------------- split the weights into hi/lo bf16 ----------------
__global__ __launch_bounds__(256) void cvt_w(const float* __restrict__ Wqkv,
                                             const float* __restrict__ Wg,
                                             const float* __restrict__ Wo)
{
    int i = blockIdx.x * 256 + threadIdx.x;   // 0..81919
    float x;
    bf16 *H, *L;
    int off;
    if (i < 49152)      { x = Wqkv[i];        H = g_wqkv_h; L = g_wqkv_l; off = i; }
    else if (i < 65536) { x = Wg[i - 49152];  H = g_wg_h;   L = g_wg_l;   off = i - 49152; }
    else                { x = Wo[i - 65536];  H = g_wo_h;   L = g_wo_l;   off = i - 65536; }
    bf16 h = __float2bfloat16(x);
    H[off] = h;
    L[off] = __float2bfloat16(x - __bfloat162float(h));
}

// ---------------- tensor-core GEMM: C[M x Nw] = (Ah+Al)[M x 128] @ (Bh+Bl)[128 x Nw]
#define AS_STR 40
#define BS_STR 40

#define MMA16816(d, a, b0v, b1v)                                             \
  asm volatile("mma.sync.aligned.m16n8k16.row.col.f32.bf16.bf16.f32 "        \
    "{%0,%1,%2,%3}, {%4,%5,%6,%7}, {%8,%9}, {%0,%1,%2,%3};"                  \
    : "+f"(d[0]), "+f"(d[1]), "+f"(d[2]), "+f"(d[3])                         \
    : "r"(a[0]), "r"(a[1]), "r"(a[2]), "r"(a[3]), "r"(b0v), "r"(b1v))

__global__ __launch_bounds__(256) void mma_gemm(
    const bf16* __restrict__ Ah, const bf16* __restrict__ Al,
    const bf16* __restrict__ Bh, const bf16* __restrict__ Bl,
    float* __restrict__ C, int Nw, int do_sig)
{
    __shared__ bf16 Ash[128 * AS_STR], Asl[128 * AS_STR];
    __shared__ bf16 Bsh[128 * BS_STR], Bsl[128 * BS_STR];
    const int tid  = threadIdx.x;
    const int wid  = tid >> 5, lane = tid & 31;
    const int m0   = blockIdx.x * 128;
    const int n0   = blockIdx.y * 128;
    const int wm   = (wid & 3) * 32;
    const int wn   = (wid >> 2) * 64;
    const int lr   = lane >> 2;          // 0..7
    const int lc   = lane & 3;           // 0..3

    float acc[2][8][4];
    #pragma unroll
    for (int mt = 0; mt < 2; ++mt)
        #pragma unroll
        for (int nt = 0; nt < 8; ++nt)
            #pragma unroll
            for (int e = 0; e < 4; ++e) acc[mt][nt][e] = 0.0f;

    for (int kc = 0; kc < 4; ++kc) {
        #pragma unroll
        for (int it = 0; it < 2; ++it) {
            int idx = tid + it * 256;
            int row = idx >> 2, kq = idx & 3;
            uint4 vh = *(const uint4*)(Ah + (size_t)(m0 + row) * 128 + kc * 32 + kq * 8);
            *(uint4*)&Ash[row * AS_STR + kq * 8] = vh;
            uint4 vl = *(const uint4*)(Al + (size_t)(m0 + row) * 128 + kc * 32 + kq * 8);
            *(uint4*)&Asl[row * AS_STR + kq * 8] = vl;
        }
        #pragma unroll
        for (int it = 0; it < 2; ++it) {
            int idx = tid + it * 256;
            int k = idx >> 4, nq = idx & 15;
            int sw = k ^ (2 * nq);
            uint4 vh = *(const uint4*)(Bh + (size_t)(kc * 32 + k) * Nw + n0 + nq * 8);
            uint4 vl = *(const uint4*)(Bl + (size_t)(kc * 32 + k) * Nw + n0 + nq * 8);
            bf16 th[8], tl[8];
            *(uint4*)th = vh; *(uint4*)tl = vl;
            #pragma unroll
            for (int e = 0; e < 8; ++e) {
                Bsh[(nq * 8 + e) * BS_STR + sw] = th[e];
                Bsl[(nq * 8 + e) * BS_STR + sw] = tl[e];
            }
        }
        __syncthreads();

        #pragma unroll
        for (int kh = 0; kh < 2; ++kh) {
            const int kb = kh * 16;
            uint32_t afh[2][4], afl[2][4];
            #pragma unroll
            for (int mt = 0; mt < 2; ++mt) {
                int r = wm + mt * 16 + lr;
                int kcol = kb + lc * 2;
                afh[mt][0] = *(const uint32_t*)&Ash[ r      * AS_STR + kcol];
                afh[mt][1] = *(const uint32_t*)&Ash[(r + 8) * AS_STR + kcol];
                afh[mt][2] = *(const uint32_t*)&Ash[ r      * AS_STR + kcol + 8];
                afh[mt][3] = *(const uint32_t*)&Ash[(r + 8) * AS_STR + kcol + 8];
                afl[mt][0] = *(const uint32_t*)&Asl[ r      * AS_STR + kcol];
                afl[mt][1] = *(const uint32_t*)&Asl[(r + 8) * AS_STR + kcol];
                afl[mt][2] = *(const uint32_t*)&Asl[ r      * AS_STR + kcol + 8];
                afl[mt][3] = *(const uint32_t*)&Asl[(r + 8) * AS_STR + kcol + 8];
            }
            #pragma unroll
            for (int nt = 0; nt < 8; ++nt) {
                int n   = wn + nt * 8 + lr;
                int s   = 2 * ((n >> 3) & 15);
                int c0  = kb + lc * 2;
                uint32_t bh0 = *(const uint32_t*)&Bsh[n * BS_STR + ( c0      ^ s)];
                uint32_t bh1 = *(const uint32_t*)&Bsh[n * BS_STR + ((c0 + 8) ^ s)];
                uint32_t bl0 = *(const uint32_t*)&Bsl[n * BS_STR + ( c0      ^ s)];
                uint32_t bl1 = *(const uint32_t*)&Bsl[n * BS_STR + ((c0 + 8) ^ s)];
                #pragma unroll
                for (int mt = 0; mt < 2; ++mt) {
                    MMA16816(acc[mt][nt], afh[mt], bh0, bh1);
                    MMA16816(acc[mt][nt], afh[mt], bl0, bl1);
                    MMA16816(acc[mt][nt], afl[mt], bh0, bh1);
                }
            }
        }
        __syncthreads();
    }
    #pragma unroll
    for (int mt = 0; mt < 2; ++mt) {
        size_t r = (size_t)(m0 + wm + mt * 16 + lr);
        #pragma unroll
        for (int nt = 0; nt < 8; ++nt) {
            int n = n0 + wn + nt * 8 + lc * 2;
            float2 v0 = make_float2(acc[mt][nt][0], acc[mt][nt][1]);
            float2 v1 = make_float2(acc[mt][nt][2], acc[mt][nt][3]);
            if (do_sig) {
                v0.x = 1.0f / (1.0f + __expf(-v0.x));
                v0.y = 1.0f / (1.0f + __expf(-v0.y));
                v1.x = 1.0f / (1.0f + __expf(-v1.x));
                v1.y = 1.0f / (1.0f + __expf(-v1.y));
            }
            *(float2*)(C + r * Nw + n)       = v0;
            *(float2*)(C + (r + 8) * Nw + n) = v1;
        }
    }
}

// ---------------- attention: one CTA per (i, h, 64-row j-tile) --------------
#define QS_STRIDE 68
#define KS_STRIDE 260
#define VS_STRIDE 36
#define PS_STRIDE 260
#define ATTN_SMEM ((32*QS_STRIDE + 32*KS_STRIDE + 256*VS_STRIDE + 64*PS_STRIDE) * 4)

__global__ __launch_bounds__(256) void attn_kernel()
{
    extern __shared__ float sm[];
    float* Qs = sm;
    float* Ks = Qs + 32 * QS_STRIDE;
    float* Vs = Ks + 32 * KS_STRIDE;
    float* Ps = Vs + 256 * VS_STRIDE;

    const int tid = threadIdx.x;
    const int jt  = blockIdx.x;     // 0..3
    const int h   = blockIdx.y;     // 0..3
    const int i   = blockIdx.z;     // 0..255

    const float* base = g_qkv + (size_t)i * NSEQ * 384 + h * 32;

    #pragma unroll
    for (int it = 0; it < 2; ++it) {
        int idx = tid + it * 256;
        int jj = idx >> 3, cq = idx & 7;
        float4 v = *(const float4*)(base + (size_t)(jt * 64 + jj) * 384 + cq * 4);
        Qs[(cq * 4 + 0) * QS_STRIDE + jj] = v.x;
        Qs[(cq * 4 + 1) * QS_STRIDE + jj] = v.y;
        Qs[(cq * 4 + 2) * QS_STRIDE + jj] = v.z;
        Qs[(cq * 4 + 3) * QS_STRIDE + jj] = v.w;
    }
    #pragma unroll
    for (int it = 0; it < 8; ++it) {
        int idx = tid + it * 256;
        int k = idx >> 3, cq = idx & 7;
        float4 v = *(const float4*)(base + 128 + (size_t)k * 384 + cq * 4);
        Ks[(cq * 4 + 0) * KS_STRIDE + k] = v.x;
        Ks[(cq * 4 + 1) * KS_STRIDE + k] = v.y;
        Ks[(cq * 4 + 2) * KS_STRIDE + k] = v.z;
        Ks[(cq * 4 + 3) * KS_STRIDE + k] = v.w;
        float4 w = *(const float4*)(base + 256 + (size_t)k * 384 + cq * 4);
        *(float4*)&Vs[k * VS_STRIDE + cq * 4] = w;
    }
    __syncthreads();

    // ---- phase A: S = Q K^T. Thread covers rows ty*4+0..3, cols q*64+tx*4+0..3
    // (conflict-free: 16 lanes read 16 consecutive float4s per fragment) ----
    const int tx = tid & 15, ty = tid >> 4;
    float acc[4][16];
    #pragma unroll
    for (int r = 0; r < 4; ++r)
        #pragma unroll
        for (int q = 0; q < 16; ++q) acc[r][q] = 0.0f;

    #pragma unroll 8
    for (int c = 0; c < 32; ++c) {
        float4 a  = *(const float4*)&Qs[c * QS_STRIDE + ty * 4];
        float4 b0 = *(const float4*)&Ks[c * KS_STRIDE + tx * 4 + 0];
        float4 b1 = *(const float4*)&Ks[c * KS_STRIDE + tx * 4 + 64];
        float4 b2 = *(const float4*)&Ks[c * KS_STRIDE + tx * 4 + 128];
        float4 b3 = *(const float4*)&Ks[c * KS_STRIDE + tx * 4 + 192];
        float ar[4] = {a.x, a.y, a.z, a.w};
        float bv[16] = {b0.x,b0.y,b0.z,b0.w, b1.x,b1.y,b1.z,b1.w,
                        b2.x,b2.y,b2.z,b2.w, b3.x,b3.y,b3.z,b3.w};
        #pragma unroll
        for (int r = 0; r < 4; ++r)
            #pragma unroll
            for (int q = 0; q < 16; ++q) acc[r][q] += ar[r] * bv[q];
    }

    // ---- softmax over k (16-lane groups still cover the full k=0..255) ----
    const float scale = 0.17677669529663687f;   // 1/sqrt(32)
    #pragma unroll
    for (int r = 0; r < 4; ++r) {
        int jg = jt * 64 + ty * 4 + r;
        const float* bp = g_bias + (size_t)h * NROWS + (size_t)jg * NSEQ + tx * 4;
        float4 B0 = *(const float4*)(bp + 0);
        float4 B1 = *(const float4*)(bp + 64);
        float4 B2 = *(const float4*)(bp + 128);
        float4 B3 = *(const float4*)(bp + 192);
        float bb[16] = {B0.x,B0.y,B0.z,B0.w, B1.x,B1.y,B1.z,B1.w,
                        B2.x,B2.y,B2.z,B2.w, B3.x,B3.y,B3.z,B3.w};
        float s[16];
        float mx = -1e30f;
        #pragma unroll
        for (int q = 0; q < 16; ++q) {
            s[q] = acc[r][q] * scale + bb[q];
            mx = fmaxf(mx, s[q]);
        }
        #pragma unroll
        for (int m = 8; m; m >>= 1) mx = fmaxf(mx, __shfl_xor_sync(0xffffffffu, mx, m));
        float sum = 0.0f;
        #pragma unroll
        for (int q = 0; q < 16; ++q) { s[q] = __expf(s[q] - mx); sum += s[q]; }
        #pragma unroll
        for (int m = 8; m; m >>= 1) sum += __shfl_xor_sync(0xffffffffu, sum, m);
        float inv = 1.0f / sum;
        #pragma unroll
        for (int q = 0; q < 16; ++q) s[q] *= inv;
        float* pr = &Ps[(ty * 4 + r) * PS_STRIDE + tx * 4];
        *(float4*)(pr + 0)   = make_float4(s[0],  s[1],  s[2],  s[3]);
        *(float4*)(pr + 64)  = make_float4(s[4],  s[5],  s[6],  s[7]);
        *(float4*)(pr + 128) = make_float4(s[8],  s[9],  s[10], s[11]);
        *(float4*)(pr + 192) = make_float4(s[12], s[13], s[14], s[15]);
    }
    __syncthreads();

    // ---- phase B: O = P V (64x32), thread = 4 rows x 2 cols ----
    const int txB = tid & 15, tyB = tid >> 4;
    float o[4][2] = {};
    #pragma unroll 4
    for (int k = 0; k < 256; k += 4) {
        float4 p[4];
        #pragma unroll
        for (int r = 0; r < 4; ++r)
            p[r] = *(const float4*)&Ps[(tyB * 4 + r) * PS_STRIDE + k];
        float2 v[4];
        #pragma unroll
        for (int kk = 0; kk < 4; ++kk)
            v[kk] = *(const float2*)&Vs[(k + kk) * VS_STRIDE + txB * 2];
        #pragma unroll
        for (int r = 0; r < 4; ++r) {
            o[r][0] += p[r].x * v[0].x + p[r].y * v[1].x + p[r].z * v[2].x + p[r].w * v[3].x;
            o[r][1] += p[r].x * v[0].y + p[r].y * v[1].y + p[r].z * v[2].y + p[r].w * v[3].y;
        }
    }
    // gate + bf16 hi/lo split store
    #pragma unroll
    for (int r = 0; r < 4; ++r) {
        int jg = jt * 64 + tyB * 4 + r;
        size_t row = (size_t)i * NSEQ + jg;
        float2 gt = *(const float2*)(g_gate + row * 128 + h * 32 + txB * 2);
        float x0 = o[r][0] * gt.x;
        float x1 = o[r][1] * gt.y;
        bf16 h0 = __float2bfloat16(x0);
        bf16 h1 = __float2bfloat16(x1);
        bf16 l0 = __float2bfloat16(x0 - __bfloat162float(h0));
        bf16 l1 = __float2bfloat16(x1 - __bfloat162float(h1));
        __nv_bfloat162 ph; ph.x = h0; ph.y = h1;
        __nv_bfloat162 pl; pl.x = l0; pl.y = l1;
        *(__nv_bfloat162*)(g_go_h + row * 128 + h * 32 + txB * 2) = ph;
        *(__nv_bfloat162*)(g_go_l + row * 128 + h * 32 + txB * 2) = pl;
    }
}

// ---------------- launch ----------------
extern "C" void kernel_launch(void* const* d_in, const int* in_sizes, int n_in,
                              void* d_out, int out_size)
{
    const float* z    = (const float*)d_in[0];
    const float* ln_g = (const float*)d_in[1];
    const float* ln_b = (const float*)d_in[2];
    const float* Wqkv = (const float*)d_in[3];
    const float* Wb   = (const float*)d_in[4];
    const float* Wg   = (const float*)d_in[5];
    const float* Wo   = (const float*)d_in[6];
    float* out = (float*)d_out;

    cudaFuncSetAttribute(attn_kernel, cudaFuncAttributeMaxDynamicSharedMemorySize, ATTN_SMEM);

    void *pznh, *pznl, *pqkv, *pgate, *pgoh, *pgol;
    void *pwqh, *pwql, *pwgh, *pwgl, *pwoh, *pwol;
    cudaGetSymbolAddress(&pznh, g_zn_h);
    cudaGetSymbolAddress(&pznl, g_zn_l);
    cudaGetSymbolAddress(&pqkv, g_qkv);
    cudaGetSymbolAddress(&pgate, g_gate);
    cudaGetSymbolAddress(&pgoh, g_go_h);
    cudaGetSymbolAddress(&pgol, g_go_l);
    cudaGetSymbolAddress(&pwqh, g_wqkv_h);
    cudaGetSymbolAddress(&pwql, g_wqkv_l);
    cudaGetSymbolAddress(&pwgh, g_wg_h);
    cudaGetSymbolAddress(&pwgl, g_wg_l);
    cudaGetSymbolAddress(&pwoh, g_wo_h);
    cudaGetSymbolAddress(&pwol, g_wo_l);

    ln_kernel<<<NROWS / 8, 256>>>(z, ln_g, ln_b, Wb);
    cvt_w<<<320, 256>>>(Wqkv, Wg, Wo);
    // qkv = zn @ Wqkv  (65536 x 384)
    mma_gemm<<<dim3(NROWS / 128, 3), 256>>>((const bf16*)pznh, (const bf16*)pznl,
                                            (const bf16*)pwqh, (const bf16*)pwql,
                                            (float*)pqkv, 384, 0);
    // gate = sigmoid(zn @ Wg)  (65536 x 128)
    mma_gemm<<<dim3(NROWS / 128, 1), 256>>>((const bf16*)pznh, (const bf16*)pznl,
                                            (const bf16*)pwgh, (const bf16*)pwgl,
                                            (float*)pgate, 128, 1);
    attn_kernel<<<dim3(4, 4, 256), 256, ATTN_SMEM>>>();
    // out = (gate*o) @ Wo  (65536 x 128)
    mma_gemm<<<dim3(NROWS / 128, 1), 256>>>((const bf16*)pgoh, (const bf16*)pgol,
                                            (const bf16*)pwoh, (const bf16*)pwol,
                                            out, 128, 0);
}

// round 9
// speedup vs baseline: 1.9660x; 1.4018x over previous
#include <cuda_runtime.h>
#include <cuda_bf16.h>
#include <cstdint>
#include <math.h>

typedef __nv_bfloat16 bf16;

#define NSEQ 256
#define CZ   128
#define NHEAD 4
#define CHEAD 32
#define NROWS (NSEQ*NSEQ)   // 65536

// ---------------- scratch (static __device__, no allocation) ----------------
__device__ bf16  g_zn_h[(size_t)NROWS * CZ];
__device__ bf16  g_zn_l[(size_t)NROWS * CZ];
__device__ bf16  g_qkvh[(size_t)NROWS * 3 * CZ];    // hi(q|k|v)  50 MB
__device__ bf16  g_qkvl[(size_t)NROWS * 3 * CZ];    // lo(q|k|v)  50 MB
__device__ float g_gate[(size_t)NROWS * CZ];
__device__ float g_bias[(size_t)NHEAD * NROWS];     // [h][row]
__device__ bf16  g_go_h[(size_t)NROWS * CZ];
__device__ bf16  g_go_l[(size_t)NROWS * CZ];
// split weights
__device__ bf16 g_wqkv_h[128 * 384], g_wqkv_l[128 * 384];
__device__ bf16 g_wg_h  [128 * 128], g_wg_l  [128 * 128];
__device__ bf16 g_wo_h  [128 * 128], g_wo_l  [128 * 128];

// ---------------- LayerNorm + bf16 split + fused pair-bias ----------------
__global__ __launch_bounds__(256) void ln_kernel(const float* __restrict__ z,
                                                 const float* __restrict__ gam,
                                                 const float* __restrict__ bet,
                                                 const float* __restrict__ Wb)
{
    int row  = (blockIdx.x * blockDim.x + threadIdx.x) >> 5;
    int lane = threadIdx.x & 31;
    float4 v = *(const float4*)(z + (size_t)row * CZ + lane * 4);
    float s  = v.x + v.y + v.z + v.w;
    float ss = v.x*v.x + v.y*v.y + v.z*v.z + v.w*v.w;
    #pragma unroll
    for (int m = 16; m; m >>= 1) {
        s  += __shfl_xor_sync(0xffffffffu, s,  m);
        ss += __shfl_xor_sync(0xffffffffu, ss, m);
    }
    float mu   = s * (1.0f / CZ);
    float var  = ss * (1.0f / CZ) - mu * mu;
    float rstd = rsqrtf(var + 1e-5f);
    float4 gg = *(const float4*)(gam + lane * 4);
    float4 bb = *(const float4*)(bet + lane * 4);
    float o[4];
    o[0] = (v.x - mu) * rstd * gg.x + bb.x;
    o[1] = (v.y - mu) * rstd * gg.y + bb.y;
    o[2] = (v.z - mu) * rstd * gg.z + bb.z;
    o[3] = (v.w - mu) * rstd * gg.w + bb.w;
    bf16 h[4], l[4];
    #pragma unroll
    for (int t = 0; t < 4; ++t) {
        h[t] = __float2bfloat16(o[t]);
        l[t] = __float2bfloat16(o[t] - __bfloat162float(h[t]));
    }
    *(uint2*)(g_zn_h + (size_t)row * CZ + lane * 4) = *(uint2*)h;
    *(uint2*)(g_zn_l + (size_t)row * CZ + lane * 4) = *(uint2*)l;

    const float4* W4 = (const float4*)Wb;
    float4 acc = make_float4(0.f, 0.f, 0.f, 0.f);
    #pragma unroll
    for (int t = 0; t < 4; ++t) {
        float4 w = W4[lane * 4 + t];
        acc.x += o[t] * w.x; acc.y += o[t] * w.y;
        acc.z += o[t] * w.z; acc.w += o[t] * w.w;
    }
    #pragma unroll
    for (int m = 16; m; m >>= 1) {
        acc.x += __shfl_xor_sync(0xffffffffu, acc.x, m);
        acc.y += __shfl_xor_sync(0xffffffffu, acc.y, m);
        acc.z += __shfl_xor_sync(0xffffffffu, acc.z, m);
        acc.w += __shfl_xor_sync(0xffffffffu, acc.w, m);
    }
    if (lane == 0) {
        g_bias[(size_t)0 * NROWS + row] = acc.x;
        g_bias[(size_t)1 * NROWS + row] = acc.y;
        g_bias[(size_t)2 * NROWS + row] = acc.z;
        g_bias[(size_t)3 * NROWS + row] = acc.w;
    }
}

// ---------------- split the weights into hi/lo bf16 ----------------
__global__ __launch_bounds__(256) void cvt_w(const float* __restrict__ Wqkv,
                                             const float* __restrict__ Wg,
                                             const float* __restrict__ Wo)
{
    int i = blockIdx.x * 256 + threadIdx.x;
    float x;
    bf16 *H, *L;
    int off;
    if (i < 49152)      { x = Wqkv[i];        H = g_wqkv_h; L = g_wqkv_l; off = i; }
    else if (i < 65536) { x = Wg[i - 49152];  H = g_wg_h;   L = g_wg_l;   off = i - 49152; }
    else                { x = Wo[i - 65536];  H = g_wo_h;   L = g_wo_l;   off = i - 65536; }
    bf16 h = __float2bfloat16(x);
    H[off] = h;
    L[off] = __float2bfloat16(x - __bfloat162float(h));
}

// ---------------- tensor-core GEMM ----------------
#define AS_STR 40
#define BS_STR 40

#define MMA16816(d, a, b0v, b1v)                                             \
  asm volatile("mma.sync.aligned.m16n8k16.row.col.f32.bf16.bf16.f32 "        \
    "{%0,%1,%2,%3}, {%4,%5,%6,%7}, {%8,%9}, {%0,%1,%2,%3};"                  \
    : "+f"(d[0]), "+f"(d[1]), "+f"(d[2]), "+f"(d[3])                         \
    : "r"(a[0]), "r"(a[1]), "r"(a[2]), "r"(a[3]), "r"(b0v), "r"(b1v))

// mode 0: f32 out; mode 1: f32 + sigmoid; mode 2: split bf16 out (Ch, Cl)
__global__ __launch_bounds__(256) void mma_gemm(
    const bf16* __restrict__ Ah, const bf16* __restrict__ Al,
    const bf16* __restrict__ Bh, const bf16* __restrict__ Bl,
    float* __restrict__ C, bf16* __restrict__ Ch, bf16* __restrict__ Cl,
    int Nw, int mode)
{
    __shared__ bf16 Ash[128 * AS_STR], Asl[128 * AS_STR];
    __shared__ bf16 Bsh[128 * BS_STR], Bsl[128 * BS_STR];
    const int tid  = threadIdx.x;
    const int wid  = tid >> 5, lane = tid & 31;
    const int m0   = blockIdx.x * 128;
    const int n0   = blockIdx.y * 128;
    const int wm   = (wid & 3) * 32;
    const int wn   = (wid >> 2) * 64;
    const int lr   = lane >> 2;
    const int lc   = lane & 3;

    float acc[2][8][4];
    #pragma unroll
    for (int mt = 0; mt < 2; ++mt)
        #pragma unroll
        for (int nt = 0; nt < 8; ++nt)
            #pragma unroll
            for (int e = 0; e < 4; ++e) acc[mt][nt][e] = 0.0f;

    for (int kc = 0; kc < 4; ++kc) {
        #pragma unroll
        for (int it = 0; it < 2; ++it) {
            int idx = tid + it * 256;
            int row = idx >> 2, kq = idx & 3;
            uint4 vh = *(const uint4*)(Ah + (size_t)(m0 + row) * 128 + kc * 32 + kq * 8);
            *(uint4*)&Ash[row * AS_STR + kq * 8] = vh;
            uint4 vl = *(const uint4*)(Al + (size_t)(m0 + row) * 128 + kc * 32 + kq * 8);
            *(uint4*)&Asl[row * AS_STR + kq * 8] = vl;
        }
        #pragma unroll
        for (int it = 0; it < 2; ++it) {
            int idx = tid + it * 256;
            int k = idx >> 4, nq = idx & 15;
            int sw = k ^ (2 * nq);
            uint4 vh = *(const uint4*)(Bh + (size_t)(kc * 32 + k) * Nw + n0 + nq * 8);
            uint4 vl = *(const uint4*)(Bl + (size_t)(kc * 32 + k) * Nw + n0 + nq * 8);
            bf16 th[8], tl[8];
            *(uint4*)th = vh; *(uint4*)tl = vl;
            #pragma unroll
            for (int e = 0; e < 8; ++e) {
                Bsh[(nq * 8 + e) * BS_STR + sw] = th[e];
                Bsl[(nq * 8 + e) * BS_STR + sw] = tl[e];
            }
        }
        __syncthreads();

        #pragma unroll
        for (int kh = 0; kh < 2; ++kh) {
            const int kb = kh * 16;
            uint32_t afh[2][4], afl[2][4];
            #pragma unroll
            for (int mt = 0; mt < 2; ++mt) {
                int r = wm + mt * 16 + lr;
                int kcol = kb + lc * 2;
                afh[mt][0] = *(const uint32_t*)&Ash[ r      * AS_STR + kcol];
                afh[mt][1] = *(const uint32_t*)&Ash[(r + 8) * AS_STR + kcol];
                afh[mt][2] = *(const uint32_t*)&Ash[ r      * AS_STR + kcol + 8];
                afh[mt][3] = *(const uint32_t*)&Ash[(r + 8) * AS_STR + kcol + 8];
                afl[mt][0] = *(const uint32_t*)&Asl[ r      * AS_STR + kcol];
                afl[mt][1] = *(const uint32_t*)&Asl[(r + 8) * AS_STR + kcol];
                afl[mt][2] = *(const uint32_t*)&Asl[ r      * AS_STR + kcol + 8];
                afl[mt][3] = *(const uint32_t*)&Asl[(r + 8) * AS_STR + kcol + 8];
            }
            #pragma unroll
            for (int nt = 0; nt < 8; ++nt) {
                int n   = wn + nt * 8 + lr;
                int s   = 2 * ((n >> 3) & 15);
                int c0  = kb + lc * 2;
                uint32_t bh0 = *(const uint32_t*)&Bsh[n * BS_STR + ( c0      ^ s)];
                uint32_t bh1 = *(const uint32_t*)&Bsh[n * BS_STR + ((c0 + 8) ^ s)];
                uint32_t bl0 = *(const uint32_t*)&Bsl[n * BS_STR + ( c0      ^ s)];
                uint32_t bl1 = *(const uint32_t*)&Bsl[n * BS_STR + ((c0 + 8) ^ s)];
                #pragma unroll
                for (int mt = 0; mt < 2; ++mt) {
                    MMA16816(acc[mt][nt], afh[mt], bh0, bh1);
                    MMA16816(acc[mt][nt], afh[mt], bl0, bl1);
                    MMA16816(acc[mt][nt], afl[mt], bh0, bh1);
                }
            }
        }
        __syncthreads();
    }
    #pragma unroll
    for (int mt = 0; mt < 2; ++mt) {
        size_t r = (size_t)(m0 + wm + mt * 16 + lr);
        #pragma unroll
        for (int nt = 0; nt < 8; ++nt) {
            int n = n0 + wn + nt * 8 + lc * 2;
            float2 v0 = make_float2(acc[mt][nt][0], acc[mt][nt][1]);
            float2 v1 = make_float2(acc[mt][nt][2], acc[mt][nt][3]);
            if (mode == 1) {
                v0.x = 1.0f / (1.0f + __expf(-v0.x));
                v0.y = 1.0f / (1.0f + __expf(-v0.y));
                v1.x = 1.0f / (1.0f + __expf(-v1.x));
                v1.y = 1.0f / (1.0f + __expf(-v1.y));
            }
            if (mode == 2) {
                __nv_bfloat162 h0 = __floats2bfloat162_rn(v0.x, v0.y);
                __nv_bfloat162 l0 = __floats2bfloat162_rn(v0.x - __bfloat162float(h0.x),
                                                          v0.y - __bfloat162float(h0.y));
                __nv_bfloat162 h1 = __floats2bfloat162_rn(v1.x, v1.y);
                __nv_bfloat162 l1 = __floats2bfloat162_rn(v1.x - __bfloat162float(h1.x),
                                                          v1.y - __bfloat162float(h1.y));
                *(__nv_bfloat162*)(Ch + r * Nw + n)       = h0;
                *(__nv_bfloat162*)(Cl + r * Nw + n)       = l0;
                *(__nv_bfloat162*)(Ch + (r + 8) * Nw + n) = h1;
                *(__nv_bfloat162*)(Cl + (r + 8) * Nw + n) = l1;
            } else {
                *(float2*)(C + r * Nw + n)       = v0;
                *(float2*)(C + (r + 8) * Nw + n) = v1;
            }
        }
    }
}

// ---------------- tensor-core attention ----------------
// CTA = (jt 64-row j-tile, h, i); 256 thr, 8 warps as 4(m) x 2(n).
// warp tile: 16 j-rows x 128 k-cols.
#define QS_STR 40
#define KS_STR 40
#define VT_STR 264
#define ATTN_SMEM ((64*QS_STR*2 + 256*KS_STR*2 + 32*VT_STR*2) * 2 + 64*4*4 + 64*32*4)

__global__ __launch_bounds__(256) void attn_kernel()
{
    extern __shared__ char smraw[];
    bf16*  Qh   = (bf16*)smraw;
    bf16*  Ql   = Qh + 64 * QS_STR;
    bf16*  Kh   = Ql + 64 * QS_STR;
    bf16*  Kl   = Kh + 256 * KS_STR;
    bf16*  Vth  = Kl + 256 * KS_STR;
    bf16*  Vtl  = Vth + 32 * VT_STR;
    float* stats = (float*)(Vtl + 32 * VT_STR);   // [64 rows][2 wn][max,sum]
    float* obuf  = stats + 64 * 4;                // [64 rows][32 c]

    const int tid = threadIdx.x;
    const int wid = tid >> 5, lane = tid & 31;
    const int lr  = lane >> 2, lc = lane & 3;
    const int wm  = (wid & 3) * 16;
    const int wn  = wid >> 2;                     // 0 or 1
    const int jt  = blockIdx.x;
    const int h   = blockIdx.y;
    const int i   = blockIdx.z;
    const int i_row0 = i * NSEQ;

    // ---- stage Q (64x32), K (256x32), Vt (32x256) hi+lo ----
    {
        int j = tid >> 2, cq = tid & 3;
        size_t src = (size_t)(i_row0 + jt * 64 + j) * 384 + h * 32 + cq * 8;
        *(uint4*)&Qh[j * QS_STR + cq * 8] = *(const uint4*)(g_qkvh + src);
        *(uint4*)&Ql[j * QS_STR + cq * 8] = *(const uint4*)(g_qkvl + src);
    }
    #pragma unroll
    for (int it = 0; it < 4; ++it) {
        int idx = tid + it * 256;
        int k = idx >> 2, cq = idx & 3;
        size_t src = (size_t)(i_row0 + k) * 384 + h * 32 + cq * 8;
        *(uint4*)&Kh[k * KS_STR + cq * 8] = *(const uint4*)(g_qkvh + src + 128);
        *(uint4*)&Kl[k * KS_STR + cq * 8] = *(const uint4*)(g_qkvl + src + 128);
        uint4 vh = *(const uint4*)(g_qkvh + src + 256);
        uint4 vl = *(const uint4*)(g_qkvl + src + 256);
        bf16 th[8], tl[8];
        *(uint4*)th = vh; *(uint4*)tl = vl;
        #pragma unroll
        for (int e = 0; e < 8; ++e) {
            Vth[(cq * 8 + e) * VT_STR + k] = th[e];
            Vtl[(cq * 8 + e) * VT_STR + k] = tl[e];
        }
    }
    __syncthreads();

    // ---- scores: S = Q K^T  (warp: 16 x 128, acc[16 nt][4]) ----
    float acc[16][4];
    #pragma unroll
    for (int nt = 0; nt < 16; ++nt)
        #pragma unroll
        for (int e = 0; e < 4; ++e) acc[nt][e] = 0.0f;

    uint32_t qfh[2][4], qfl[2][4];
    #pragma unroll
    for (int kt = 0; kt < 2; ++kt) {
        int r = wm + lr;
        int c = kt * 16 + lc * 2;
        qfh[kt][0] = *(const uint32_t*)&Qh[ r      * QS_STR + c];
        qfh[kt][1] = *(const uint32_t*)&Qh[(r + 8) * QS_STR + c];
        qfh[kt][2] = *(const uint32_t*)&Qh[ r      * QS_STR + c + 8];
        qfh[kt][3] = *(const uint32_t*)&Qh[(r + 8) * QS_STR + c + 8];
        qfl[kt][0] = *(const uint32_t*)&Ql[ r      * QS_STR + c];
        qfl[kt][1] = *(const uint32_t*)&Ql[(r + 8) * QS_STR + c];
        qfl[kt][2] = *(const uint32_t*)&Ql[ r      * QS_STR + c + 8];
        qfl[kt][3] = *(const uint32_t*)&Ql[(r + 8) * QS_STR + c + 8];
    }
    #pragma unroll
    for (int nt = 0; nt < 16; ++nt) {
        int n = wn * 128 + nt * 8 + lr;
        #pragma unroll
        for (int kt = 0; kt < 2; ++kt) {
            int c = kt * 16 + lc * 2;
            uint32_t bh0 = *(const uint32_t*)&Kh[n * KS_STR + c];
            uint32_t bh1 = *(const uint32_t*)&Kh[n * KS_STR + c + 8];
            uint32_t bl0 = *(const uint32_t*)&Kl[n * KS_STR + c];
            uint32_t bl1 = *(const uint32_t*)&Kl[n * KS_STR + c + 8];
            MMA16816(acc[nt], qfh[kt], bh0, bh1);
            MMA16816(acc[nt], qfh[kt], bl0, bl1);
            MMA16816(acc[nt], qfl[kt], bh0, bh1);
        }
    }

    // ---- softmax over k (bias from gmem; rows lr & lr+8) ----
    const float scale = 0.17677669529663687f;   // 1/sqrt(32)
    const int jg1 = jt * 64 + wm + lr;
    const int jg2 = jg1 + 8;
    const float* bp1 = g_bias + (size_t)h * NROWS + (size_t)jg1 * NSEQ + wn * 128;
    const float* bp2 = g_bias + (size_t)h * NROWS + (size_t)jg2 * NSEQ + wn * 128;
    float mx1 = -1e30f, mx2 = -1e30f;
    #pragma unroll
    for (int nt = 0; nt < 16; ++nt) {
        float2 b1 = *(const float2*)(bp1 + nt * 8 + lc * 2);
        float2 b2 = *(const float2*)(bp2 + nt * 8 + lc * 2);
        acc[nt][0] = acc[nt][0] * scale + b1.x;
        acc[nt][1] = acc[nt][1] * scale + b1.y;
        acc[nt][2] = acc[nt][2] * scale + b2.x;
        acc[nt][3] = acc[nt][3] * scale + b2.y;
        mx1 = fmaxf(mx1, fmaxf(acc[nt][0], acc[nt][1]));
        mx2 = fmaxf(mx2, fmaxf(acc[nt][2], acc[nt][3]));
    }
    mx1 = fmaxf(mx1, __shfl_xor_sync(0xffffffffu, mx1, 1));
    mx1 = fmaxf(mx1, __shfl_xor_sync(0xffffffffu, mx1, 2));
    mx2 = fmaxf(mx2, __shfl_xor_sync(0xffffffffu, mx2, 1));
    mx2 = fmaxf(mx2, __shfl_xor_sync(0xffffffffu, mx2, 2));
    float sm1 = 0.f, sm2 = 0.f;
    #pragma unroll
    for (int nt = 0; nt < 16; ++nt) {
        acc[nt][0] = __expf(acc[nt][0] - mx1);
        acc[nt][1] = __expf(acc[nt][1] - mx1);
        acc[nt][2] = __expf(acc[nt][2] - mx2);
        acc[nt][3] = __expf(acc[nt][3] - mx2);
        sm1 += acc[nt][0] + acc[nt][1];
        sm2 += acc[nt][2] + acc[nt][3];
    }
    sm1 += __shfl_xor_sync(0xffffffffu, sm1, 1);
    sm1 += __shfl_xor_sync(0xffffffffu, sm1, 2);
    sm2 += __shfl_xor_sync(0xffffffffu, sm2, 1);
    sm2 += __shfl_xor_sync(0xffffffffu, sm2, 2);
    if (lc == 0) {
        stats[(wm + lr)     * 4 + wn * 2 + 0] = mx1;
        stats[(wm + lr)     * 4 + wn * 2 + 1] = sm1;
        stats[(wm + lr + 8) * 4 + wn * 2 + 0] = mx2;
        stats[(wm + lr + 8) * 4 + wn * 2 + 1] = sm2;
    }
    __syncthreads();
    float corr1, corr2;
    {
        float ma = stats[(wm + lr) * 4 + 0], sa = stats[(wm + lr) * 4 + 1];
        float mb = stats[(wm + lr) * 4 + 2], sb = stats[(wm + lr) * 4 + 3];
        float M = fmaxf(ma, mb);
        float den = sa * __expf(ma - M) + sb * __expf(mb - M);
        corr1 = __expf(mx1 - M) / den;
        ma = stats[(wm + lr + 8) * 4 + 0]; sa = stats[(wm + lr + 8) * 4 + 1];
        mb = stats[(wm + lr + 8) * 4 + 2]; sb = stats[(wm + lr + 8) * 4 + 3];
        M = fmaxf(ma, mb);
        den = sa * __expf(ma - M) + sb * __expf(mb - M);
        corr2 = __expf(mx2 - M) / den;
    }

    // ---- P V: reuse acc as A-fragments (hi + lo split) ----
    float oacc[4][4];
    #pragma unroll
    for (int cn = 0; cn < 4; ++cn)
        #pragma unroll
        for (int e = 0; e < 4; ++e) oacc[cn][e] = 0.0f;

    #pragma unroll
    for (int kt = 0; kt < 8; ++kt) {
        int nt0 = 2 * kt, nt1 = 2 * kt + 1;
        float p[8];
        p[0] = acc[nt0][0] * corr1; p[1] = acc[nt0][1] * corr1;
        p[2] = acc[nt0][2] * corr2; p[3] = acc[nt0][3] * corr2;
        p[4] = acc[nt1][0] * corr1; p[5] = acc[nt1][1] * corr1;
        p[6] = acc[nt1][2] * corr2; p[7] = acc[nt1][3] * corr2;
        uint32_t ah[4], al[4];
        #pragma unroll
        for (int q = 0; q < 4; ++q) {
            __nv_bfloat162 hh = __floats2bfloat162_rn(p[q * 2], p[q * 2 + 1]);
            __nv_bfloat162 ll = __floats2bfloat162_rn(p[q * 2]     - __bfloat162float(hh.x),
                                                      p[q * 2 + 1] - __bfloat162float(hh.y));
            ah[q] = *(uint32_t*)&hh;
            al[q] = *(uint32_t*)&ll;
        }
        int kb = wn * 128 + kt * 16;
        #pragma unroll
        for (int cn = 0; cn < 4; ++cn) {
            int c = cn * 8 + lr;
            uint32_t bh0 = *(const uint32_t*)&Vth[c * VT_STR + kb + lc * 2];
            uint32_t bh1 = *(const uint32_t*)&Vth[c * VT_STR + kb + 8 + lc * 2];
            uint32_t bl0 = *(const uint32_t*)&Vtl[c * VT_STR + kb + lc * 2];
            uint32_t bl1 = *(const uint32_t*)&Vtl[c * VT_STR + kb + 8 + lc * 2];
            MMA16816(oacc[cn], ah, bh0, bh1);
            MMA16816(oacc[cn], ah, bl0, bl1);
            MMA16816(oacc[cn], al, bh0, bh1);
        }
    }

    // ---- reduce the 2 n-warps, gate, split-store ----
    if (wn == 1) {
        #pragma unroll
        for (int cn = 0; cn < 4; ++cn) {
            *(float2*)&obuf[(wm + lr)     * 32 + cn * 8 + lc * 2] = make_float2(oacc[cn][0], oacc[cn][1]);
            *(float2*)&obuf[(wm + lr + 8) * 32 + cn * 8 + lc * 2] = make_float2(oacc[cn][2], oacc[cn][3]);
        }
    }
    __syncthreads();
    if (wn == 0) {
        size_t row1 = (size_t)(i_row0 + jg1) * 128 + h * 32;
        size_t row2 = (size_t)(i_row0 + jg2) * 128 + h * 32;
        #pragma unroll
        for (int cn = 0; cn < 4; ++cn) {
            int c = cn * 8 + lc * 2;
            float2 p1 = *(const float2*)&obuf[(wm + lr)     * 32 + c];
            float2 p2 = *(const float2*)&obuf[(wm + lr + 8) * 32 + c];
            float2 g1 = *(const float2*)(g_gate + row1 + c);
            float2 g2 = *(const float2*)(g_gate + row2 + c);
            float x0 = (oacc[cn][0] + p1.x) * g1.x;
            float x1 = (oacc[cn][1] + p1.y) * g1.y;
            float x2 = (oacc[cn][2] + p2.x) * g2.x;
            float x3 = (oacc[cn][3] + p2.y) * g2.y;
            __nv_bfloat162 h1 = __floats2bfloat162_rn(x0, x1);
            __nv_bfloat162 l1 = __floats2bfloat162_rn(x0 - __bfloat162float(h1.x),
                                                      x1 - __bfloat162float(h1.y));
            __nv_bfloat162 h2 = __floats2bfloat162_rn(x2, x3);
            __nv_bfloat162 l2 = __floats2bfloat162_rn(x2 - __bfloat162float(h2.x),
                                                      x3 - __bfloat162float(h2.y));
            *(__nv_bfloat162*)(g_go_h + row1 + c) = h1;
            *(__nv_bfloat162*)(g_go_l + row1 + c) = l1;
            *(__nv_bfloat162*)(g_go_h + row2 + c) = h2;
            *(__nv_bfloat162*)(g_go_l + row2 + c) = l2;
        }
    }
}

// ---------------- launch ----------------
extern "C" void kernel_launch(void* const* d_in, const int* in_sizes, int n_in,
                              void* d_out, int out_size)
{
    const float* z    = (const float*)d_in[0];
    const float* ln_g = (const float*)d_in[1];
    const float* ln_b = (const float*)d_in[2];
    const float* Wqkv = (const float*)d_in[3];
    const float* Wb   = (const float*)d_in[4];
    const float* Wg   = (const float*)d_in[5];
    const float* Wo   = (const float*)d_in[6];
    float* out = (float*)d_out;

    cudaFuncSetAttribute(attn_kernel, cudaFuncAttributeMaxDynamicSharedMemorySize, ATTN_SMEM);

    void *pznh, *pznl, *pqh, *pql, *pgate, *pgoh, *pgol;
    void *pwqh, *pwql, *pwgh, *pwgl, *pwoh, *pwol;
    cudaGetSymbolAddress(&pznh, g_zn_h);
    cudaGetSymbolAddress(&pznl, g_zn_l);
    cudaGetSymbolAddress(&pqh,  g_qkvh);
    cudaGetSymbolAddress(&pql,  g_qkvl);
    cudaGetSymbolAddress(&pgate, g_gate);
    cudaGetSymbolAddress(&pgoh, g_go_h);
    cudaGetSymbolAddress(&pgol, g_go_l);
    cudaGetSymbolAddress(&pwqh, g_wqkv_h);
    cudaGetSymbolAddress(&pwql, g_wqkv_l);
    cudaGetSymbolAddress(&pwgh, g_wg_h);
    cudaGetSymbolAddress(&pwgl, g_wg_l);
    cudaGetSymbolAddress(&pwoh, g_wo_h);
    cudaGetSymbolAddress(&pwol, g_wo_l);

    ln_kernel<<<NROWS / 8, 256>>>(z, ln_g, ln_b, Wb);
    cvt_w<<<320, 256>>>(Wqkv, Wg, Wo);
    // qkv = zn @ Wqkv  -> split bf16
    mma_gemm<<<dim3(NROWS / 128, 3), 256>>>((const bf16*)pznh, (const bf16*)pznl,
                                            (const bf16*)pwqh, (const bf16*)pwql,
                                            nullptr, (bf16*)pqh, (bf16*)pql, 384, 2);
    // gate = sigmoid(zn @ Wg) -> f32
    mma_gemm<<<dim3(NROWS / 128, 1), 256>>>((const bf16*)pznh, (const bf16*)pznl,
                                            (const bf16*)pwgh, (const bf16*)pwgl,
                                            (float*)pgate, nullptr, nullptr, 128, 1);
    attn_kernel<<<dim3(4, 4, 256), 256, ATTN_SMEM>>>();
    // out = (gate*o) @ Wo -> f32
    mma_gemm<<<dim3(NROWS / 128, 1), 256>>>((const bf16*)pgoh, (const bf16*)pgol,
                                            (const bf16*)pwoh, (const bf16*)pwol,
                                            out, nullptr, nullptr, 128, 0);
}

// round 12
// speedup vs baseline: 2.2302x; 1.1344x over previous
#include <cuda_runtime.h>
#include <cuda_bf16.h>
#include <cstdint>
#include <math.h>

typedef __nv_bfloat16 bf16;

#define NSEQ 256
#define CZ   128
#define NHEAD 4
#define CHEAD 32
#define NROWS (NSEQ*NSEQ)   // 65536

// ---------------- scratch (static __device__, no allocation) ----------------
__device__ bf16  g_zn_h[(size_t)NROWS * CZ];
__device__ bf16  g_zn_l[(size_t)NROWS * CZ];
__device__ bf16  g_qkvh[(size_t)NROWS * 3 * CZ];    // hi(q|k|v)
__device__ bf16  g_qkvl[(size_t)NROWS * 3 * CZ];    // lo(q|k|v)
__device__ float g_gate[(size_t)NROWS * CZ];
__device__ float g_bias[(size_t)NHEAD * NROWS];     // [h][j*256+k]
__device__ bf16  g_go_h[(size_t)NROWS * CZ];
__device__ bf16  g_go_l[(size_t)NROWS * CZ];
// split weights: wcat = [Wqkv | Wg]  (128 x 512), wo (128 x 128)
__device__ bf16 g_wcat_h[128 * 512], g_wcat_l[128 * 512];
__device__ bf16 g_wo_h  [128 * 128], g_wo_l  [128 * 128];

// ---------------- LayerNorm + bf16 split + fused pair-bias ----------------
__global__ __launch_bounds__(256) void ln_kernel(const float* __restrict__ z,
                                                 const float* __restrict__ gam,
                                                 const float* __restrict__ bet,
                                                 const float* __restrict__ Wb)
{
    int row  = (blockIdx.x * blockDim.x + threadIdx.x) >> 5;
    int lane = threadIdx.x & 31;
    float4 v = *(const float4*)(z + (size_t)row * CZ + lane * 4);
    float s  = v.x + v.y + v.z + v.w;
    float ss = v.x*v.x + v.y*v.y + v.z*v.z + v.w*v.w;
    #pragma unroll
    for (int m = 16; m; m >>= 1) {
        s  += __shfl_xor_sync(0xffffffffu, s,  m);
        ss += __shfl_xor_sync(0xffffffffu, ss, m);
    }
    float mu   = s * (1.0f / CZ);
    float var  = ss * (1.0f / CZ) - mu * mu;
    float rstd = rsqrtf(var + 1e-5f);
    float4 gg = *(const float4*)(gam + lane * 4);
    float4 bb = *(const float4*)(bet + lane * 4);
    float o[4];
    o[0] = (v.x - mu) * rstd * gg.x + bb.x;
    o[1] = (v.y - mu) * rstd * gg.y + bb.y;
    o[2] = (v.z - mu) * rstd * gg.z + bb.z;
    o[3] = (v.w - mu) * rstd * gg.w + bb.w;
    bf16 h[4], l[4];
    #pragma unroll
    for (int t = 0; t < 4; ++t) {
        h[t] = __float2bfloat16(o[t]);
        l[t] = __float2bfloat16(o[t] - __bfloat162float(h[t]));
    }
    *(uint2*)(g_zn_h + (size_t)row * CZ + lane * 4) = *(uint2*)h;
    *(uint2*)(g_zn_l + (size_t)row * CZ + lane * 4) = *(uint2*)l;

    const float4* W4 = (const float4*)Wb;
    float4 acc = make_float4(0.f, 0.f, 0.f, 0.f);
    #pragma unroll
    for (int t = 0; t < 4; ++t) {
        float4 w = W4[lane * 4 + t];
        acc.x += o[t] * w.x; acc.y += o[t] * w.y;
        acc.z += o[t] * w.z; acc.w += o[t] * w.w;
    }
    #pragma unroll
    for (int m = 16; m; m >>= 1) {
        acc.x += __shfl_xor_sync(0xffffffffu, acc.x, m);
        acc.y += __shfl_xor_sync(0xffffffffu, acc.y, m);
        acc.z += __shfl_xor_sync(0xffffffffu, acc.z, m);
        acc.w += __shfl_xor_sync(0xffffffffu, acc.w, m);
    }
    if (lane == 0) {
        g_bias[(size_t)0 * NROWS + row] = acc.x;
        g_bias[(size_t)1 * NROWS + row] = acc.y;
        g_bias[(size_t)2 * NROWS + row] = acc.z;
        g_bias[(size_t)3 * NROWS + row] = acc.w;
    }
}

// ---------------- split weights into hi/lo bf16 (combined layout) ----------
__global__ __launch_bounds__(256) void cvt_w(const float* __restrict__ Wqkv,
                                             const float* __restrict__ Wg,
                                             const float* __restrict__ Wo)
{
    int i = blockIdx.x * 256 + threadIdx.x;   // 0..81919
    float x;
    bf16 *H, *L;
    int off;
    if (i < 65536) {
        int r = i >> 9, c = i & 511;
        x = (c < 384) ? Wqkv[r * 384 + c] : Wg[r * 128 + (c - 384)];
        H = g_wcat_h; L = g_wcat_l; off = i;
    } else {
        off = i - 65536;
        x = Wo[off];
        H = g_wo_h; L = g_wo_l;
    }
    bf16 h = __float2bfloat16(x);
    H[off] = h;
    L[off] = __float2bfloat16(x - __bfloat162float(h));
}

// ---------------- tensor-core GEMM ----------------
#define AS_STR 40
#define BS_STR 40

#define MMA16816(d, a, b0v, b1v)                                             \
  asm volatile("mma.sync.aligned.m16n8k16.row.col.f32.bf16.bf16.f32 "        \
    "{%0,%1,%2,%3}, {%4,%5,%6,%7}, {%8,%9}, {%0,%1,%2,%3};"                  \
    : "+f"(d[0]), "+f"(d[1]), "+f"(d[2]), "+f"(d[3])                         \
    : "r"(a[0]), "r"(a[1]), "r"(a[2]), "r"(a[3]), "r"(b0v), "r"(b1v))

// mode 0: f32 out (stride Nw)
// mode 3: combined qkv|gate: n<384 -> split bf16 (stride 384); n>=384 -> sigmoid f32 (stride 128)
__global__ __launch_bounds__(256) void mma_gemm(
    const bf16* __restrict__ Ah, const bf16* __restrict__ Al,
    const bf16* __restrict__ Bh, const bf16* __restrict__ Bl,
    float* __restrict__ C, bf16* __restrict__ Ch, bf16* __restrict__ Cl,
    int Nw, int mode)
{
    __shared__ bf16 Ash[128 * AS_STR], Asl[128 * AS_STR];
    __shared__ bf16 Bsh[128 * BS_STR], Bsl[128 * BS_STR];
    const int tid  = threadIdx.x;
    const int wid  = tid >> 5, lane = tid & 31;
    const int m0   = blockIdx.x * 128;
    const int n0   = blockIdx.y * 128;
    const int wm   = (wid & 3) * 32;
    const int wn   = (wid >> 2) * 64;
    const int lr   = lane >> 2;
    const int lc   = lane & 3;

    float acc[2][8][4];
    #pragma unroll
    for (int mt = 0; mt < 2; ++mt)
        #pragma unroll
        for (int nt = 0; nt < 8; ++nt)
            #pragma unroll
            for (int e = 0; e < 4; ++e) acc[mt][nt][e] = 0.0f;

    for (int kc = 0; kc < 4; ++kc) {
        #pragma unroll
        for (int it = 0; it < 2; ++it) {
            int idx = tid + it * 256;
            int row = idx >> 2, kq = idx & 3;
            uint4 vh = *(const uint4*)(Ah + (size_t)(m0 + row) * 128 + kc * 32 + kq * 8);
            *(uint4*)&Ash[row * AS_STR + kq * 8] = vh;
            uint4 vl = *(const uint4*)(Al + (size_t)(m0 + row) * 128 + kc * 32 + kq * 8);
            *(uint4*)&Asl[row * AS_STR + kq * 8] = vl;
        }
        #pragma unroll
        for (int it = 0; it < 2; ++it) {
            int idx = tid + it * 256;
            int k = idx >> 4, nq = idx & 15;
            int sw = k ^ (2 * nq);
            uint4 vh = *(const uint4*)(Bh + (size_t)(kc * 32 + k) * Nw + n0 + nq * 8);
            uint4 vl = *(const uint4*)(Bl + (size_t)(kc * 32 + k) * Nw + n0 + nq * 8);
            bf16 th[8], tl[8];
            *(uint4*)th = vh; *(uint4*)tl = vl;
            #pragma unroll
            for (int e = 0; e < 8; ++e) {
                Bsh[(nq * 8 + e) * BS_STR + sw] = th[e];
                Bsl[(nq * 8 + e) * BS_STR + sw] = tl[e];
            }
        }
        __syncthreads();

        #pragma unroll
        for (int kh = 0; kh < 2; ++kh) {
            const int kb = kh * 16;
            uint32_t afh[2][4], afl[2][4];
            #pragma unroll
            for (int mt = 0; mt < 2; ++mt) {
                int r = wm + mt * 16 + lr;
                int kcol = kb + lc * 2;
                afh[mt][0] = *(const uint32_t*)&Ash[ r      * AS_STR + kcol];
                afh[mt][1] = *(const uint32_t*)&Ash[(r + 8) * AS_STR + kcol];
                afh[mt][2] = *(const uint32_t*)&Ash[ r      * AS_STR + kcol + 8];
                afh[mt][3] = *(const uint32_t*)&Ash[(r + 8) * AS_STR + kcol + 8];
                afl[mt][0] = *(const uint32_t*)&Asl[ r      * AS_STR + kcol];
                afl[mt][1] = *(const uint32_t*)&Asl[(r + 8) * AS_STR + kcol];
                afl[mt][2] = *(const uint32_t*)&Asl[ r      * AS_STR + kcol + 8];
                afl[mt][3] = *(const uint32_t*)&Asl[(r + 8) * AS_STR + kcol + 8];
            }
            #pragma unroll
            for (int nt = 0; nt < 8; ++nt) {
                int n   = wn + nt * 8 + lr;
                int s   = 2 * ((n >> 3) & 15);
                int c0  = kb + lc * 2;
                uint32_t bh0 = *(const uint32_t*)&Bsh[n * BS_STR + ( c0      ^ s)];
                uint32_t bh1 = *(const uint32_t*)&Bsh[n * BS_STR + ((c0 + 8) ^ s)];
                uint32_t bl0 = *(const uint32_t*)&Bsl[n * BS_STR + ( c0      ^ s)];
                uint32_t bl1 = *(const uint32_t*)&Bsl[n * BS_STR + ((c0 + 8) ^ s)];
                #pragma unroll
                for (int mt = 0; mt < 2; ++mt) {
                    MMA16816(acc[mt][nt], afh[mt], bh0, bh1);
                    MMA16816(acc[mt][nt], afh[mt], bl0, bl1);
                    MMA16816(acc[mt][nt], afl[mt], bh0, bh1);
                }
            }
        }
        __syncthreads();
    }
    const int qkv_blk = (mode == 3) && (n0 < 384);
    const int gate_blk = (mode == 3) && (n0 >= 384);
    #pragma unroll
    for (int mt = 0; mt < 2; ++mt) {
        size_t r = (size_t)(m0 + wm + mt * 16 + lr);
        #pragma unroll
        for (int nt = 0; nt < 8; ++nt) {
            int n = n0 + wn + nt * 8 + lc * 2;
            float2 v0 = make_float2(acc[mt][nt][0], acc[mt][nt][1]);
            float2 v1 = make_float2(acc[mt][nt][2], acc[mt][nt][3]);
            if (qkv_blk) {
                __nv_bfloat162 h0 = __floats2bfloat162_rn(v0.x, v0.y);
                __nv_bfloat162 l0 = __floats2bfloat162_rn(v0.x - __bfloat162float(h0.x),
                                                          v0.y - __bfloat162float(h0.y));
                __nv_bfloat162 h1 = __floats2bfloat162_rn(v1.x, v1.y);
                __nv_bfloat162 l1 = __floats2bfloat162_rn(v1.x - __bfloat162float(h1.x),
                                                          v1.y - __bfloat162float(h1.y));
                *(__nv_bfloat162*)(Ch + r * 384 + n)       = h0;
                *(__nv_bfloat162*)(Cl + r * 384 + n)       = l0;
                *(__nv_bfloat162*)(Ch + (r + 8) * 384 + n) = h1;
                *(__nv_bfloat162*)(Cl + (r + 8) * 384 + n) = l1;
            } else if (gate_blk) {
                int c = n - 384;
                v0.x = 1.0f / (1.0f + __expf(-v0.x));
                v0.y = 1.0f / (1.0f + __expf(-v0.y));
                v1.x = 1.0f / (1.0f + __expf(-v1.x));
                v1.y = 1.0f / (1.0f + __expf(-v1.y));
                *(float2*)(C + r * 128 + c)       = v0;
                *(float2*)(C + (r + 8) * 128 + c) = v1;
            } else {
                *(float2*)(C + r * Nw + n)       = v0;
                *(float2*)(C + (r + 8) * Nw + n) = v1;
            }
        }
    }
}

// ---------------- tensor-core attention, warp-autonomous rows ----------------
// CTA = (jt in {0,1} -> 128 j-rows, h, i); 256 thr, 8 warps; warp owns 16 rows
// x full k=256, processed as two 128-halves with online softmax.
#define QS_STR 40
#define KS_STR 40
#define VT_STR 264
#define ATTN_SMEM ((128*QS_STR + 256*KS_STR + 32*VT_STR) * 2 * 2)

__global__ __launch_bounds__(256, 2) void attn_kernel()
{
    extern __shared__ char smraw[];
    bf16* Qh  = (bf16*)smraw;               // 128 x QS_STR
    bf16* Ql  = Qh + 128 * QS_STR;
    bf16* Kh  = Ql + 128 * QS_STR;          // 256 x KS_STR
    bf16* Kl  = Kh + 256 * KS_STR;
    bf16* Vth = Kl + 256 * KS_STR;          // 32 x VT_STR  [c][k]
    bf16* Vtl = Vth + 32 * VT_STR;

    const int tid = threadIdx.x;
    const int wid = tid >> 5, lane = tid & 31;
    const int lr  = lane >> 2, lc = lane & 3;
    const int wm  = wid * 16;
    const int jt  = blockIdx.x;             // 0..1
    const int h   = blockIdx.y;
    const int i   = blockIdx.z;
    const int i_row0 = i * NSEQ;

    // ---- stage Q (128x32), K (256x32), Vt (32x256), hi+lo ----
    #pragma unroll
    for (int it = 0; it < 2; ++it) {
        int idx = tid + it * 256;
        int j = idx >> 2, cq = idx & 3;
        size_t src = (size_t)(i_row0 + jt * 128 + j) * 384 + h * 32 + cq * 8;
        *(uint4*)&Qh[j * QS_STR + cq * 8] = *(const uint4*)(g_qkvh + src);
        *(uint4*)&Ql[j * QS_STR + cq * 8] = *(const uint4*)(g_qkvl + src);
    }
    #pragma unroll
    for (int it = 0; it < 4; ++it) {
        int idx = tid + it * 256;
        int k = idx >> 2, cq = idx & 3;
        size_t src = (size_t)(i_row0 + k) * 384 + h * 32 + cq * 8;
        *(uint4*)&Kh[k * KS_STR + cq * 8] = *(const uint4*)(g_qkvh + src + 128);
        *(uint4*)&Kl[k * KS_STR + cq * 8] = *(const uint4*)(g_qkvl + src + 128);
        uint4 vh = *(const uint4*)(g_qkvh + src + 256);
        uint4 vl = *(const uint4*)(g_qkvl + src + 256);
        bf16 th[8], tl[8];
        *(uint4*)th = vh; *(uint4*)tl = vl;
        #pragma unroll
        for (int e = 0; e < 8; ++e) {
            Vth[(cq * 8 + e) * VT_STR + k] = th[e];
            Vtl[(cq * 8 + e) * VT_STR + k] = tl[e];
        }
    }
    __syncthreads();

    // ---- Q fragments (rows wm+lr, wm+lr+8) ----
    uint32_t qfh[2][4], qfl[2][4];
    #pragma unroll
    for (int kt = 0; kt < 2; ++kt) {
        int r = wm + lr;
        int c = kt * 16 + lc * 2;
        qfh[kt][0] = *(const uint32_t*)&Qh[ r      * QS_STR + c];
        qfh[kt][1] = *(const uint32_t*)&Qh[(r + 8) * QS_STR + c];
        qfh[kt][2] = *(const uint32_t*)&Qh[ r      * QS_STR + c + 8];
        qfh[kt][3] = *(const uint32_t*)&Qh[(r + 8) * QS_STR + c + 8];
        qfl[kt][0] = *(const uint32_t*)&Ql[ r      * QS_STR + c];
        qfl[kt][1] = *(const uint32_t*)&Ql[(r + 8) * QS_STR + c];
        qfl[kt][2] = *(const uint32_t*)&Ql[ r      * QS_STR + c + 8];
        qfl[kt][3] = *(const uint32_t*)&Ql[(r + 8) * QS_STR + c + 8];
    }

    const float scale = 0.17677669529663687f;   // 1/sqrt(32)
    const int jg1 = jt * 128 + wm + lr;         // global j of row pair
    const int jg2 = jg1 + 8;
    const float* brow1 = g_bias + (size_t)h * NROWS + (size_t)jg1 * NSEQ;
    const float* brow2 = g_bias + (size_t)h * NROWS + (size_t)jg2 * NSEQ;

    float m1 = -1e30f, m2 = -1e30f, s1 = 0.0f, s2 = 0.0f;
    float oacc[4][4];
    #pragma unroll
    for (int cn = 0; cn < 4; ++cn)
        #pragma unroll
        for (int e = 0; e < 4; ++e) oacc[cn][e] = 0.0f;

    #pragma unroll
    for (int half = 0; half < 2; ++half) {
        const int kh0 = half * 128;
        float acc[16][4];
        #pragma unroll
        for (int nt = 0; nt < 16; ++nt)
            #pragma unroll
            for (int e = 0; e < 4; ++e) acc[nt][e] = 0.0f;

        // S = Q K^T for this half
        #pragma unroll
        for (int nt = 0; nt < 16; ++nt) {
            int n = kh0 + nt * 8 + lr;
            #pragma unroll
            for (int kt = 0; kt < 2; ++kt) {
                int c = kt * 16 + lc * 2;
                uint32_t bh0 = *(const uint32_t*)&Kh[n * KS_STR + c];
                uint32_t bh1 = *(const uint32_t*)&Kh[n * KS_STR + c + 8];
                uint32_t bl0 = *(const uint32_t*)&Kl[n * KS_STR + c];
                uint32_t bl1 = *(const uint32_t*)&Kl[n * KS_STR + c + 8];
                MMA16816(acc[nt], qfh[kt], bh0, bh1);
                MMA16816(acc[nt], qfh[kt], bl0, bl1);
                MMA16816(acc[nt], qfl[kt], bh0, bh1);
            }
        }

        // scale + bias, local max
        float lmx1 = -1e30f, lmx2 = -1e30f;
        #pragma unroll
        for (int nt = 0; nt < 16; ++nt) {
            int col = kh0 + nt * 8 + lc * 2;
            float2 b1 = *(const float2*)(brow1 + col);
            float2 b2 = *(const float2*)(brow2 + col);
            acc[nt][0] = acc[nt][0] * scale + b1.x;
            acc[nt][1] = acc[nt][1] * scale + b1.y;
            acc[nt][2] = acc[nt][2] * scale + b2.x;
            acc[nt][3] = acc[nt][3] * scale + b2.y;
            lmx1 = fmaxf(lmx1, fmaxf(acc[nt][0], acc[nt][1]));
            lmx2 = fmaxf(lmx2, fmaxf(acc[nt][2], acc[nt][3]));
        }
        lmx1 = fmaxf(lmx1, __shfl_xor_sync(0xffffffffu, lmx1, 1));
        lmx1 = fmaxf(lmx1, __shfl_xor_sync(0xffffffffu, lmx1, 2));
        lmx2 = fmaxf(lmx2, __shfl_xor_sync(0xffffffffu, lmx2, 1));
        lmx2 = fmaxf(lmx2, __shfl_xor_sync(0xffffffffu, lmx2, 2));

        float m1n = fmaxf(m1, lmx1), m2n = fmaxf(m2, lmx2);
        float f1 = __expf(m1 - m1n), f2 = __expf(m2 - m2n);
        float ls1 = 0.0f, ls2 = 0.0f;
        #pragma unroll
        for (int nt = 0; nt < 16; ++nt) {
            acc[nt][0] = __expf(acc[nt][0] - m1n);
            acc[nt][1] = __expf(acc[nt][1] - m1n);
            acc[nt][2] = __expf(acc[nt][2] - m2n);
            acc[nt][3] = __expf(acc[nt][3] - m2n);
            ls1 += acc[nt][0] + acc[nt][1];
            ls2 += acc[nt][2] + acc[nt][3];
        }
        ls1 += __shfl_xor_sync(0xffffffffu, ls1, 1);
        ls1 += __shfl_xor_sync(0xffffffffu, ls1, 2);
        ls2 += __shfl_xor_sync(0xffffffffu, ls2, 1);
        ls2 += __shfl_xor_sync(0xffffffffu, ls2, 2);
        s1 = s1 * f1 + ls1;
        s2 = s2 * f2 + ls2;
        m1 = m1n; m2 = m2n;

        // rescale running O
        #pragma unroll
        for (int cn = 0; cn < 4; ++cn) {
            oacc[cn][0] *= f1; oacc[cn][1] *= f1;
            oacc[cn][2] *= f2; oacc[cn][3] *= f2;
        }

        // P V for this half (P from acc, hi+lo split)
        #pragma unroll
        for (int kt = 0; kt < 8; ++kt) {
            int nt0 = 2 * kt, nt1 = 2 * kt + 1;
            uint32_t ah[4], al[4];
            {
                __nv_bfloat162 hh, ll;
                hh = __floats2bfloat162_rn(acc[nt0][0], acc[nt0][1]);
                ll = __floats2bfloat162_rn(acc[nt0][0] - __bfloat162float(hh.x),
                                           acc[nt0][1] - __bfloat162float(hh.y));
                ah[0] = *(uint32_t*)&hh; al[0] = *(uint32_t*)&ll;
                hh = __floats2bfloat162_rn(acc[nt0][2], acc[nt0][3]);
                ll = __floats2bfloat162_rn(acc[nt0][2] - __bfloat162float(hh.x),
                                           acc[nt0][3] - __bfloat162float(hh.y));
                ah[1] = *(uint32_t*)&hh; al[1] = *(uint32_t*)&ll;
                hh = __floats2bfloat162_rn(acc[nt1][0], acc[nt1][1]);
                ll = __floats2bfloat162_rn(acc[nt1][0] - __bfloat162float(hh.x),
                                           acc[nt1][1] - __bfloat162float(hh.y));
                ah[2] = *(uint32_t*)&hh; al[2] = *(uint32_t*)&ll;
                hh = __floats2bfloat162_rn(acc[nt1][2], acc[nt1][3]);
                ll = __floats2bfloat162_rn(acc[nt1][2] - __bfloat162float(hh.x),
                                           acc[nt1][3] - __bfloat162float(hh.y));
                ah[3] = *(uint32_t*)&hh; al[3] = *(uint32_t*)&ll;
            }
            int kb = kh0 + kt * 16;
            #pragma unroll
            for (int cn = 0; cn < 4; ++cn) {
                int c = cn * 8 + lr;
                uint32_t bh0 = *(const uint32_t*)&Vth[c * VT_STR + kb + lc * 2];
                uint32_t bh1 = *(const uint32_t*)&Vth[c * VT_STR + kb + 8 + lc * 2];
                uint32_t bl0 = *(const uint32_t*)&Vtl[c * VT_STR + kb + lc * 2];
                uint32_t bl1 = *(const uint32_t*)&Vtl[c * VT_STR + kb + 8 + lc * 2];
                MMA16816(oacc[cn], ah, bh0, bh1);
                MMA16816(oacc[cn], ah, bl0, bl1);
                MMA16816(oacc[cn], al, bh0, bh1);
            }
        }
    }

    // ---- normalize, gate, split-store (warp-local, no barrier) ----
    float inv1 = 1.0f / s1, inv2 = 1.0f / s2;
    size_t row1 = (size_t)(i_row0 + jg1) * 128 + h * 32;
    size_t row2 = (size_t)(i_row0 + jg2) * 128 + h * 32;
    #pragma unroll
    for (int cn = 0; cn < 4; ++cn) {
        int c = cn * 8 + lc * 2;
        float2 g1 = *(const float2*)(g_gate + row1 + c);
        float2 g2 = *(const float2*)(g_gate + row2 + c);
        float x0 = oacc[cn][0] * inv1 * g1.x;
        float x1 = oacc[cn][1] * inv1 * g1.y;
        float x2 = oacc[cn][2] * inv2 * g2.x;
        float x3 = oacc[cn][3] * inv2 * g2.y;
        __nv_bfloat162 h1 = __floats2bfloat162_rn(x0, x1);
        __nv_bfloat162 l1 = __floats2bfloat162_rn(x0 - __bfloat162float(h1.x),
                                                  x1 - __bfloat162float(h1.y));
        __nv_bfloat162 h2 = __floats2bfloat162_rn(x2, x3);
        __nv_bfloat162 l2 = __floats2bfloat162_rn(x2 - __bfloat162float(h2.x),
                                                  x3 - __bfloat162float(h2.y));
        *(__nv_bfloat162*)(g_go_h + row1 + c) = h1;
        *(__nv_bfloat162*)(g_go_l + row1 + c) = l1;
        *(__nv_bfloat162*)(g_go_h + row2 + c) = h2;
        *(__nv_bfloat162*)(g_go_l + row2 + c) = l2;
    }
}

// ---------------- launch ----------------
extern "C" void kernel_launch(void* const* d_in, const int* in_sizes, int n_in,
                              void* d_out, int out_size)
{
    const float* z    = (const float*)d_in[0];
    const float* ln_g = (const float*)d_in[1];
    const float* ln_b = (const float*)d_in[2];
    const float* Wqkv = (const float*)d_in[3];
    const float* Wb   = (const float*)d_in[4];
    const float* Wg   = (const float*)d_in[5];
    const float* Wo   = (const float*)d_in[6];
    float* out = (float*)d_out;

    cudaFuncSetAttribute(attn_kernel, cudaFuncAttributeMaxDynamicSharedMemorySize, ATTN_SMEM);

    void *pznh, *pznl, *pqh, *pql, *pgate, *pgoh, *pgol;
    void *pwch, *pwcl, *pwoh, *pwol;
    cudaGetSymbolAddress(&pznh, g_zn_h);
    cudaGetSymbolAddress(&pznl, g_zn_l);
    cudaGetSymbolAddress(&pqh,  g_qkvh);
    cudaGetSymbolAddress(&pql,  g_qkvl);
    cudaGetSymbolAddress(&pgate, g_gate);
    cudaGetSymbolAddress(&pgoh, g_go_h);
    cudaGetSymbolAddress(&pgol, g_go_l);
    cudaGetSymbolAddress(&pwch, g_wcat_h);
    cudaGetSymbolAddress(&pwcl, g_wcat_l);
    cudaGetSymbolAddress(&pwoh, g_wo_h);
    cudaGetSymbolAddress(&pwol, g_wo_l);

    ln_kernel<<<NROWS / 8, 256>>>(z, ln_g, ln_b, Wb);
    cvt_w<<<320, 256>>>(Wqkv, Wg, Wo);
    // fused: qkv (split bf16) + gate (sigmoid f32) from combined weight
    mma_gemm<<<dim3(NROWS / 128, 4), 256>>>((const bf16*)pznh, (const bf16*)pznl,
                                            (const bf16*)pwch, (const bf16*)pwcl,
                                            (float*)pgate, (bf16*)pqh, (bf16*)pql, 512, 3);
    attn_kernel<<<dim3(2, 4, 256), 256, ATTN_SMEM>>>();
    // out = (gate*o) @ Wo -> f32
    mma_gemm<<<dim3(NROWS / 128, 1), 256>>>((const bf16*)pgoh, (const bf16*)pgol,
                                            (const bf16*)pwoh, (const bf16*)pwol,
                                            out, nullptr, nullptr, 128, 0);
}

// round 13
// speedup vs baseline: 2.4067x; 1.0792x over previous
#include <cuda_runtime.h>
#include <cuda_bf16.h>
#include <cstdint>
#include <math.h>

typedef __nv_bfloat16 bf16;

#define NSEQ 256
#define CZ   128
#define NHEAD 4
#define CHEAD 32
#define NROWS (NSEQ*NSEQ)   // 65536
#define LOG2E 1.4426950408889634f

#define CP_ASYNC16(dst, src) \
    asm volatile("cp.async.ca.shared.global [%0], [%1], 16;" :: "r"(dst), "l"(src))
#define CP_COMMIT() asm volatile("cp.async.commit_group;")
#define CP_WAIT(n)  asm volatile("cp.async.wait_group %0;" :: "n"(n))

__device__ __forceinline__ uint32_t smaddr(const void* p) {
    return (uint32_t)__cvta_generic_to_shared(p);
}
__device__ __forceinline__ float ex2(float x) {
    float r; asm("ex2.approx.ftz.f32 %0, %1;" : "=f"(r) : "f"(x)); return r;
}

// ---------------- scratch (static __device__, no allocation) ----------------
__device__ bf16  g_zn_h[(size_t)NROWS * CZ];
__device__ bf16  g_zn_l[(size_t)NROWS * CZ];
__device__ bf16  g_qkvh[(size_t)NROWS * 3 * CZ];
__device__ bf16  g_qkvl[(size_t)NROWS * 3 * CZ];
__device__ float g_gate[(size_t)NROWS * CZ];
__device__ float g_bias[(size_t)NHEAD * NROWS];     // [h][j*256+k], pre-scaled by log2e
__device__ bf16  g_go_h[(size_t)NROWS * CZ];
__device__ bf16  g_go_l[(size_t)NROWS * CZ];
__device__ bf16 g_wcat_h[128 * 512], g_wcat_l[128 * 512];
__device__ bf16 g_wo_h  [128 * 128], g_wo_l  [128 * 128];

// ---------------- LayerNorm + bf16 split + fused pair-bias (x log2e) --------
__global__ __launch_bounds__(256) void ln_kernel(const float* __restrict__ z,
                                                 const float* __restrict__ gam,
                                                 const float* __restrict__ bet,
                                                 const float* __restrict__ Wb)
{
    int row  = (blockIdx.x * blockDim.x + threadIdx.x) >> 5;
    int lane = threadIdx.x & 31;
    float4 v = *(const float4*)(z + (size_t)row * CZ + lane * 4);
    float s  = v.x + v.y + v.z + v.w;
    float ss = v.x*v.x + v.y*v.y + v.z*v.z + v.w*v.w;
    #pragma unroll
    for (int m = 16; m; m >>= 1) {
        s  += __shfl_xor_sync(0xffffffffu, s,  m);
        ss += __shfl_xor_sync(0xffffffffu, ss, m);
    }
    float mu   = s * (1.0f / CZ);
    float var  = ss * (1.0f / CZ) - mu * mu;
    float rstd = rsqrtf(var + 1e-5f);
    float4 gg = *(const float4*)(gam + lane * 4);
    float4 bb = *(const float4*)(bet + lane * 4);
    float o[4];
    o[0] = (v.x - mu) * rstd * gg.x + bb.x;
    o[1] = (v.y - mu) * rstd * gg.y + bb.y;
    o[2] = (v.z - mu) * rstd * gg.z + bb.z;
    o[3] = (v.w - mu) * rstd * gg.w + bb.w;
    bf16 h[4], l[4];
    #pragma unroll
    for (int t = 0; t < 4; ++t) {
        h[t] = __float2bfloat16(o[t]);
        l[t] = __float2bfloat16(o[t] - __bfloat162float(h[t]));
    }
    *(uint2*)(g_zn_h + (size_t)row * CZ + lane * 4) = *(uint2*)h;
    *(uint2*)(g_zn_l + (size_t)row * CZ + lane * 4) = *(uint2*)l;

    const float4* W4 = (const float4*)Wb;
    float4 acc = make_float4(0.f, 0.f, 0.f, 0.f);
    #pragma unroll
    for (int t = 0; t < 4; ++t) {
        float4 w = W4[lane * 4 + t];
        acc.x += o[t] * w.x; acc.y += o[t] * w.y;
        acc.z += o[t] * w.z; acc.w += o[t] * w.w;
    }
    #pragma unroll
    for (int m = 16; m; m >>= 1) {
        acc.x += __shfl_xor_sync(0xffffffffu, acc.x, m);
        acc.y += __shfl_xor_sync(0xffffffffu, acc.y, m);
        acc.z += __shfl_xor_sync(0xffffffffu, acc.z, m);
        acc.w += __shfl_xor_sync(0xffffffffu, acc.w, m);
    }
    if (lane == 0) {
        g_bias[(size_t)0 * NROWS + row] = acc.x * LOG2E;
        g_bias[(size_t)1 * NROWS + row] = acc.y * LOG2E;
        g_bias[(size_t)2 * NROWS + row] = acc.z * LOG2E;
        g_bias[(size_t)3 * NROWS + row] = acc.w * LOG2E;
    }
}

// ---------------- split weights into hi/lo bf16 (combined layout) ----------
__global__ __launch_bounds__(256) void cvt_w(const float* __restrict__ Wqkv,
                                             const float* __restrict__ Wg,
                                             const float* __restrict__ Wo)
{
    int i = blockIdx.x * 256 + threadIdx.x;   // 0..81919
    float x;
    bf16 *H, *L;
    int off;
    if (i < 65536) {
        int r = i >> 9, c = i & 511;
        x = (c < 384) ? Wqkv[r * 384 + c] : Wg[r * 128 + (c - 384)];
        H = g_wcat_h; L = g_wcat_l; off = i;
    } else {
        off = i - 65536;
        x = Wo[off];
        H = g_wo_h; L = g_wo_l;
    }
    bf16 h = __float2bfloat16(x);
    H[off] = h;
    L[off] = __float2bfloat16(x - __bfloat162float(h));
}

// ---------------- tensor-core GEMM, 2-stage cp.async pipeline ----------------
#define AS_STR 40
#define GSTG   20480                    // bf16 per stage (4 arrays x 128*40)
#define OFF_ASL 5120
#define OFF_BSH 10240
#define OFF_BSL 15360
#define GEMM_SMEM (2 * GSTG * 2)        // 80 KB

#define MMA16816(d, a, b0v, b1v)                                             \
  asm volatile("mma.sync.aligned.m16n8k16.row.col.f32.bf16.bf16.f32 "        \
    "{%0,%1,%2,%3}, {%4,%5,%6,%7}, {%8,%9}, {%0,%1,%2,%3};"                  \
    : "+f"(d[0]), "+f"(d[1]), "+f"(d[2]), "+f"(d[3])                         \
    : "r"(a[0]), "r"(a[1]), "r"(a[2]), "r"(a[3]), "r"(b0v), "r"(b1v))

#define GEMM_STAGE_A(kc, s)                                                  \
  { _Pragma("unroll")                                                        \
    for (int it = 0; it < 2; ++it) {                                         \
        int row = (tid >> 2) + it * 64, kq = tid & 3;                        \
        size_t so = (size_t)(m0 + row) * 128 + (kc) * 32 + kq * 8;           \
        uint32_t d = smaddr(gsm + (s) * GSTG + row * AS_STR + kq * 8);       \
        CP_ASYNC16(d, Ah + so);                                              \
        CP_ASYNC16(d + OFF_ASL * 2, Al + so);                                \
    } }

#define GEMM_LDB(kc)                                                         \
  { _Pragma("unroll")                                                        \
    for (int it = 0; it < 2; ++it) {                                         \
        int k = (tid >> 4) + it * 16, nq = tid & 15;                         \
        size_t so = (size_t)((kc) * 32 + k) * Nw + n0 + nq * 8;              \
        pbh[it] = *(const uint4*)(Bh + so);                                  \
        pbl[it] = *(const uint4*)(Bl + so);                                  \
    } }

#define GEMM_STB(s)                                                          \
  { _Pragma("unroll")                                                        \
    for (int it = 0; it < 2; ++it) {                                         \
        int k = (tid >> 4) + it * 16, nq = tid & 15;                         \
        int sw = k ^ (2 * nq);                                               \
        bf16 th[8], tl[8];                                                   \
        *(uint4*)th = pbh[it]; *(uint4*)tl = pbl[it];                        \
        bf16* dh = gsm + (s) * GSTG + OFF_BSH;                               \
        bf16* dl = gsm + (s) * GSTG + OFF_BSL;                               \
        _Pragma("unroll")                                                    \
        for (int e = 0; e < 8; ++e) {                                        \
            dh[(nq * 8 + e) * AS_STR + sw] = th[e];                          \
            dl[(nq * 8 + e) * AS_STR + sw] = tl[e];                          \
        }                                                                    \
    } }

// mode 0: f32 out (stride Nw)
// mode 3: combined qkv|gate: n<384 -> split bf16 (stride 384); n>=384 -> sigmoid f32 (stride 128)
__global__ __launch_bounds__(256) void mma_gemm(
    const bf16* __restrict__ Ah, const bf16* __restrict__ Al,
    const bf16* __restrict__ Bh, const bf16* __restrict__ Bl,
    float* __restrict__ C, bf16* __restrict__ Ch, bf16* __restrict__ Cl,
    int Nw, int mode)
{
    extern __shared__ bf16 gsm[];
    const int tid  = threadIdx.x;
    const int wid  = tid >> 5, lane = tid & 31;
    const int m0   = blockIdx.x * 128;
    const int n0   = blockIdx.y * 128;
    const int wm   = (wid & 3) * 32;
    const int wn   = (wid >> 2) * 64;
    const int lr   = lane >> 2;
    const int lc   = lane & 3;

    float acc[2][8][4];
    #pragma unroll
    for (int mt = 0; mt < 2; ++mt)
        #pragma unroll
        for (int nt = 0; nt < 8; ++nt)
            #pragma unroll
            for (int e = 0; e < 4; ++e) acc[mt][nt][e] = 0.0f;

    uint4 pbh[2], pbl[2];

    // prologue: chunk 0
    GEMM_STAGE_A(0, 0); CP_COMMIT();
    GEMM_LDB(0);
    GEMM_STB(0);

    int buf = 0;
    for (int kc = 0; kc < 4; ++kc) {
        if (kc < 3) {
            GEMM_STAGE_A(kc + 1, buf ^ 1); CP_COMMIT();
            GEMM_LDB(kc + 1);
            CP_WAIT(1);
        } else {
            CP_WAIT(0);
        }
        __syncthreads();

        const bf16* As_h = gsm + buf * GSTG;
        const bf16* As_l = As_h + OFF_ASL;
        const bf16* Bs_h = As_h + OFF_BSH;
        const bf16* Bs_l = As_h + OFF_BSL;

        #pragma unroll
        for (int kh = 0; kh < 2; ++kh) {
            const int kb = kh * 16;
            uint32_t afh[2][4], afl[2][4];
            #pragma unroll
            for (int mt = 0; mt < 2; ++mt) {
                int r = wm + mt * 16 + lr;
                int kcol = kb + lc * 2;
                afh[mt][0] = *(const uint32_t*)&As_h[ r      * AS_STR + kcol];
                afh[mt][1] = *(const uint32_t*)&As_h[(r + 8) * AS_STR + kcol];
                afh[mt][2] = *(const uint32_t*)&As_h[ r      * AS_STR + kcol + 8];
                afh[mt][3] = *(const uint32_t*)&As_h[(r + 8) * AS_STR + kcol + 8];
                afl[mt][0] = *(const uint32_t*)&As_l[ r      * AS_STR + kcol];
                afl[mt][1] = *(const uint32_t*)&As_l[(r + 8) * AS_STR + kcol];
                afl[mt][2] = *(const uint32_t*)&As_l[ r      * AS_STR + kcol + 8];
                afl[mt][3] = *(const uint32_t*)&As_l[(r + 8) * AS_STR + kcol + 8];
            }
            #pragma unroll
            for (int nt = 0; nt < 8; ++nt) {
                int n   = wn + nt * 8 + lr;
                int s   = 2 * ((n >> 3) & 15);
                int c0  = kb + lc * 2;
                uint32_t bh0 = *(const uint32_t*)&Bs_h[n * AS_STR + ( c0      ^ s)];
                uint32_t bh1 = *(const uint32_t*)&Bs_h[n * AS_STR + ((c0 + 8) ^ s)];
                uint32_t bl0 = *(const uint32_t*)&Bs_l[n * AS_STR + ( c0      ^ s)];
                uint32_t bl1 = *(const uint32_t*)&Bs_l[n * AS_STR + ((c0 + 8) ^ s)];
                #pragma unroll
                for (int mt = 0; mt < 2; ++mt) {
                    MMA16816(acc[mt][nt], afh[mt], bh0, bh1);
                    MMA16816(acc[mt][nt], afh[mt], bl0, bl1);
                    MMA16816(acc[mt][nt], afl[mt], bh0, bh1);
                }
            }
        }
        if (kc < 3) GEMM_STB(buf ^ 1);
        __syncthreads();
        buf ^= 1;
    }

    const int qkv_blk = (mode == 3) && (n0 < 384);
    const int gate_blk = (mode == 3) && (n0 >= 384);
    #pragma unroll
    for (int mt = 0; mt < 2; ++mt) {
        size_t r = (size_t)(m0 + wm + mt * 16 + lr);
        #pragma unroll
        for (int nt = 0; nt < 8; ++nt) {
            int n = n0 + wn + nt * 8 + lc * 2;
            float2 v0 = make_float2(acc[mt][nt][0], acc[mt][nt][1]);
            float2 v1 = make_float2(acc[mt][nt][2], acc[mt][nt][3]);
            if (qkv_blk) {
                __nv_bfloat162 h0 = __floats2bfloat162_rn(v0.x, v0.y);
                __nv_bfloat162 l0 = __floats2bfloat162_rn(v0.x - __bfloat162float(h0.x),
                                                          v0.y - __bfloat162float(h0.y));
                __nv_bfloat162 h1 = __floats2bfloat162_rn(v1.x, v1.y);
                __nv_bfloat162 l1 = __floats2bfloat162_rn(v1.x - __bfloat162float(h1.x),
                                                          v1.y - __bfloat162float(h1.y));
                *(__nv_bfloat162*)(Ch + r * 384 + n)       = h0;
                *(__nv_bfloat162*)(Cl + r * 384 + n)       = l0;
                *(__nv_bfloat162*)(Ch + (r + 8) * 384 + n) = h1;
                *(__nv_bfloat162*)(Cl + (r + 8) * 384 + n) = l1;
            } else if (gate_blk) {
                int c = n - 384;
                v0.x = 1.0f / (1.0f + ex2(-v0.x * LOG2E));
                v0.y = 1.0f / (1.0f + ex2(-v0.y * LOG2E));
                v1.x = 1.0f / (1.0f + ex2(-v1.x * LOG2E));
                v1.y = 1.0f / (1.0f + ex2(-v1.y * LOG2E));
                *(float2*)(C + r * 128 + c)       = v0;
                *(float2*)(C + (r + 8) * 128 + c) = v1;
            } else {
                *(float2*)(C + r * Nw + n)       = v0;
                *(float2*)(C + (r + 8) * Nw + n) = v1;
            }
        }
    }
}

// ---------------- tensor-core attention, warp-autonomous rows ----------------
#define QS_STR 40
#define KS_STR 40
#define VT_STR 264
#define ATTN_SMEM ((128*QS_STR + 256*KS_STR + 32*VT_STR) * 2 * 2)

__global__ __launch_bounds__(256, 2) void attn_kernel()
{
    extern __shared__ char smraw[];
    bf16* Qh  = (bf16*)smraw;               // 128 x QS_STR
    bf16* Ql  = Qh + 128 * QS_STR;
    bf16* Kh  = Ql + 128 * QS_STR;          // 256 x KS_STR
    bf16* Kl  = Kh + 256 * KS_STR;
    bf16* Vth = Kl + 256 * KS_STR;          // 32 x VT_STR  [c][k]
    bf16* Vtl = Vth + 32 * VT_STR;

    const int tid = threadIdx.x;
    const int wid = tid >> 5, lane = tid & 31;
    const int lr  = lane >> 2, lc = lane & 3;
    const int wm  = wid * 16;
    const int jt  = blockIdx.x;             // 0..1
    const int h   = blockIdx.y;
    const int i   = blockIdx.z;
    const int i_row0 = i * NSEQ;

    // ---- stage Q,K via cp.async; V transposed manually (overlapped) ----
    #pragma unroll
    for (int it = 0; it < 2; ++it) {
        int idx = tid + it * 256;
        int j = idx >> 2, cq = idx & 3;
        size_t src = (size_t)(i_row0 + jt * 128 + j) * 384 + h * 32 + cq * 8;
        uint32_t d = smaddr(&Qh[j * QS_STR + cq * 8]);
        CP_ASYNC16(d, g_qkvh + src);
        CP_ASYNC16(d + 128 * QS_STR * 2, g_qkvl + src);
    }
    #pragma unroll
    for (int it = 0; it < 4; ++it) {
        int idx = tid + it * 256;
        int k = idx >> 2, cq = idx & 3;
        size_t src = (size_t)(i_row0 + k) * 384 + h * 32 + cq * 8 + 128;
        uint32_t d = smaddr(&Kh[k * KS_STR + cq * 8]);
        CP_ASYNC16(d, g_qkvh + src);
        CP_ASYNC16(d + 256 * KS_STR * 2, g_qkvl + src);
    }
    CP_COMMIT();
    #pragma unroll
    for (int it = 0; it < 4; ++it) {
        int idx = tid + it * 256;
        int k = idx >> 2, cq = idx & 3;
        size_t src = (size_t)(i_row0 + k) * 384 + h * 32 + cq * 8 + 256;
        uint4 vh = *(const uint4*)(g_qkvh + src);
        uint4 vl = *(const uint4*)(g_qkvl + src);
        bf16 th[8], tl[8];
        *(uint4*)th = vh; *(uint4*)tl = vl;
        #pragma unroll
        for (int e = 0; e < 8; ++e) {
            Vth[(cq * 8 + e) * VT_STR + k] = th[e];
            Vtl[(cq * 8 + e) * VT_STR + k] = tl[e];
        }
    }
    CP_WAIT(0);
    __syncthreads();

    // ---- Q fragments (rows wm+lr, wm+lr+8) ----
    uint32_t qfh[2][4], qfl[2][4];
    #pragma unroll
    for (int kt = 0; kt < 2; ++kt) {
        int r = wm + lr;
        int c = kt * 16 + lc * 2;
        qfh[kt][0] = *(const uint32_t*)&Qh[ r      * QS_STR + c];
        qfh[kt][1] = *(const uint32_t*)&Qh[(r + 8) * QS_STR + c];
        qfh[kt][2] = *(const uint32_t*)&Qh[ r      * QS_STR + c + 8];
        qfh[kt][3] = *(const uint32_t*)&Qh[(r + 8) * QS_STR + c + 8];
        qfl[kt][0] = *(const uint32_t*)&Ql[ r      * QS_STR + c];
        qfl[kt][1] = *(const uint32_t*)&Ql[(r + 8) * QS_STR + c];
        qfl[kt][2] = *(const uint32_t*)&Ql[ r      * QS_STR + c + 8];
        qfl[kt][3] = *(const uint32_t*)&Ql[(r + 8) * QS_STR + c + 8];
    }

    const float scaleL = 0.17677669529663687f * LOG2E;  // fold log2e: scores in log2 domain
    const int jg1 = jt * 128 + wm + lr;
    const int jg2 = jg1 + 8;
    const float* brow1 = g_bias + (size_t)h * NROWS + (size_t)jg1 * NSEQ;
    const float* brow2 = g_bias + (size_t)h * NROWS + (size_t)jg2 * NSEQ;

    float m1 = -1e30f, m2 = -1e30f, s1 = 0.0f, s2 = 0.0f;
    float oacc[4][4];
    #pragma unroll
    for (int cn = 0; cn < 4; ++cn)
        #pragma unroll
        for (int e = 0; e < 4; ++e) oacc[cn][e] = 0.0f;

    #pragma unroll
    for (int half = 0; half < 2; ++half) {
        const int kh0 = half * 128;
        float acc[16][4];
        #pragma unroll
        for (int nt = 0; nt < 16; ++nt)
            #pragma unroll
            for (int e = 0; e < 4; ++e) acc[nt][e] = 0.0f;

        #pragma unroll
        for (int nt = 0; nt < 16; ++nt) {
            int n = kh0 + nt * 8 + lr;
            #pragma unroll
            for (int kt = 0; kt < 2; ++kt) {
                int c = kt * 16 + lc * 2;
                uint32_t bh0 = *(const uint32_t*)&Kh[n * KS_STR + c];
                uint32_t bh1 = *(const uint32_t*)&Kh[n * KS_STR + c + 8];
                uint32_t bl0 = *(const uint32_t*)&Kl[n * KS_STR + c];
                uint32_t bl1 = *(const uint32_t*)&Kl[n * KS_STR + c + 8];
                MMA16816(acc[nt], qfh[kt], bh0, bh1);
                MMA16816(acc[nt], qfh[kt], bl0, bl1);
                MMA16816(acc[nt], qfl[kt], bh0, bh1);
            }
        }

        float lmx1 = -1e30f, lmx2 = -1e30f;
        #pragma unroll
        for (int nt = 0; nt < 16; ++nt) {
            int col = kh0 + nt * 8 + lc * 2;
            float2 b1 = *(const float2*)(brow1 + col);
            float2 b2 = *(const float2*)(brow2 + col);
            acc[nt][0] = acc[nt][0] * scaleL + b1.x;
            acc[nt][1] = acc[nt][1] * scaleL + b1.y;
            acc[nt][2] = acc[nt][2] * scaleL + b2.x;
            acc[nt][3] = acc[nt][3] * scaleL + b2.y;
            lmx1 = fmaxf(lmx1, fmaxf(acc[nt][0], acc[nt][1]));
            lmx2 = fmaxf(lmx2, fmaxf(acc[nt][2], acc[nt][3]));
        }
        lmx1 = fmaxf(lmx1, __shfl_xor_sync(0xffffffffu, lmx1, 1));
        lmx1 = fmaxf(lmx1, __shfl_xor_sync(0xffffffffu, lmx1, 2));
        lmx2 = fmaxf(lmx2, __shfl_xor_sync(0xffffffffu, lmx2, 1));
        lmx2 = fmaxf(lmx2, __shfl_xor_sync(0xffffffffu, lmx2, 2));

        float m1n = fmaxf(m1, lmx1), m2n = fmaxf(m2, lmx2);
        float f1 = ex2(m1 - m1n), f2 = ex2(m2 - m2n);
        float ls1 = 0.0f, ls2 = 0.0f;
        #pragma unroll
        for (int nt = 0; nt < 16; ++nt) {
            acc[nt][0] = ex2(acc[nt][0] - m1n);
            acc[nt][1] = ex2(acc[nt][1] - m1n);
            acc[nt][2] = ex2(acc[nt][2] - m2n);
            acc[nt][3] = ex2(acc[nt][3] - m2n);
            ls1 += acc[nt][0] + acc[nt][1];
            ls2 += acc[nt][2] + acc[nt][3];
        }
        ls1 += __shfl_xor_sync(0xffffffffu, ls1, 1);
        ls1 += __shfl_xor_sync(0xffffffffu, ls1, 2);
        ls2 += __shfl_xor_sync(0xffffffffu, ls2, 1);
        ls2 += __shfl_xor_sync(0xffffffffu, ls2, 2);
        s1 = s1 * f1 + ls1;
        s2 = s2 * f2 + ls2;
        m1 = m1n; m2 = m2n;

        #pragma unroll
        for (int cn = 0; cn < 4; ++cn) {
            oacc[cn][0] *= f1; oacc[cn][1] *= f1;
            oacc[cn][2] *= f2; oacc[cn][3] *= f2;
        }

        #pragma unroll
        for (int kt = 0; kt < 8; ++kt) {
            int nt0 = 2 * kt, nt1 = 2 * kt + 1;
            uint32_t ah[4], al[4];
            {
                __nv_bfloat162 hh, ll;
                hh = __floats2bfloat162_rn(acc[nt0][0], acc[nt0][1]);
                ll = __floats2bfloat162_rn(acc[nt0][0] - __bfloat162float(hh.x),
                                           acc[nt0][1] - __bfloat162float(hh.y));
                ah[0] = *(uint32_t*)&hh; al[0] = *(uint32_t*)&ll;
                hh = __floats2bfloat162_rn(acc[nt0][2], acc[nt0][3]);
                ll = __floats2bfloat162_rn(acc[nt0][2] - __bfloat162float(hh.x),
                                           acc[nt0][3] - __bfloat162float(hh.y));
                ah[1] = *(uint32_t*)&hh; al[1] = *(uint32_t*)&ll;
                hh = __floats2bfloat162_rn(acc[nt1][0], acc[nt1][1]);
                ll = __floats2bfloat162_rn(acc[nt1][0] - __bfloat162float(hh.x),
                                           acc[nt1][1] - __bfloat162float(hh.y));
                ah[2] = *(uint32_t*)&hh; al[2] = *(uint32_t*)&ll;
                hh = __floats2bfloat162_rn(acc[nt1][2], acc[nt1][3]);
                ll = __floats2bfloat162_rn(acc[nt1][2] - __bfloat162float(hh.x),
                                           acc[nt1][3] - __bfloat162float(hh.y));
                ah[3] = *(uint32_t*)&hh; al[3] = *(uint32_t*)&ll;
            }
            int kb = kh0 + kt * 16;
            #pragma unroll
            for (int cn = 0; cn < 4; ++cn) {
                int c = cn * 8 + lr;
                uint32_t bh0 = *(const uint32_t*)&Vth[c * VT_STR + kb + lc * 2];
                uint32_t bh1 = *(const uint32_t*)&Vth[c * VT_STR + kb + 8 + lc * 2];
                uint32_t bl0 = *(const uint32_t*)&Vtl[c * VT_STR + kb + lc * 2];
                uint32_t bl1 = *(const uint32_t*)&Vtl[c * VT_STR + kb + 8 + lc * 2];
                MMA16816(oacc[cn], ah, bh0, bh1);
                MMA16816(oacc[cn], ah, bl0, bl1);
                MMA16816(oacc[cn], al, bh0, bh1);
            }
        }
    }

    float inv1 = 1.0f / s1, inv2 = 1.0f / s2;
    size_t row1 = (size_t)(i_row0 + jg1) * 128 + h * 32;
    size_t row2 = (size_t)(i_row0 + jg2) * 128 + h * 32;
    #pragma unroll
    for (int cn = 0; cn < 4; ++cn) {
        int c = cn * 8 + lc * 2;
        float2 g1 = *(const float2*)(g_gate + row1 + c);
        float2 g2 = *(const float2*)(g_gate + row2 + c);
        float x0 = oacc[cn][0] * inv1 * g1.x;
        float x1 = oacc[cn][1] * inv1 * g1.y;
        float x2 = oacc[cn][2] * inv2 * g2.x;
        float x3 = oacc[cn][3] * inv2 * g2.y;
        __nv_bfloat162 h1 = __floats2bfloat162_rn(x0, x1);
        __nv_bfloat162 l1 = __floats2bfloat162_rn(x0 - __bfloat162float(h1.x),
                                                  x1 - __bfloat162float(h1.y));
        __nv_bfloat162 h2 = __floats2bfloat162_rn(x2, x3);
        __nv_bfloat162 l2 = __floats2bfloat162_rn(x2 - __bfloat162float(h2.x),
                                                  x3 - __bfloat162float(h2.y));
        *(__nv_bfloat162*)(g_go_h + row1 + c) = h1;
        *(__nv_bfloat162*)(g_go_l + row1 + c) = l1;
        *(__nv_bfloat162*)(g_go_h + row2 + c) = h2;
        *(__nv_bfloat162*)(g_go_l + row2 + c) = l2;
    }
}

// ---------------- launch ----------------
extern "C" void kernel_launch(void* const* d_in, const int* in_sizes, int n_in,
                              void* d_out, int out_size)
{
    const float* z    = (const float*)d_in[0];
    const float* ln_g = (const float*)d_in[1];
    const float* ln_b = (const float*)d_in[2];
    const float* Wqkv = (const float*)d_in[3];
    const float* Wb   = (const float*)d_in[4];
    const float* Wg   = (const float*)d_in[5];
    const float* Wo   = (const float*)d_in[6];
    float* out = (float*)d_out;

    cudaFuncSetAttribute(attn_kernel, cudaFuncAttributeMaxDynamicSharedMemorySize, ATTN_SMEM);
    cudaFuncSetAttribute(mma_gemm, cudaFuncAttributeMaxDynamicSharedMemorySize, GEMM_SMEM);

    void *pznh, *pznl, *pqh, *pql, *pgate, *pgoh, *pgol;
    void *pwch, *pwcl, *pwoh, *pwol;
    cudaGetSymbolAddress(&pznh, g_zn_h);
    cudaGetSymbolAddress(&pznl, g_zn_l);
    cudaGetSymbolAddress(&pqh,  g_qkvh);
    cudaGetSymbolAddress(&pql,  g_qkvl);
    cudaGetSymbolAddress(&pgate, g_gate);
    cudaGetSymbolAddress(&pgoh, g_go_h);
    cudaGetSymbolAddress(&pgol, g_go_l);
    cudaGetSymbolAddress(&pwch, g_wcat_h);
    cudaGetSymbolAddress(&pwcl, g_wcat_l);
    cudaGetSymbolAddress(&pwoh, g_wo_h);
    cudaGetSymbolAddress(&pwol, g_wo_l);

    ln_kernel<<<NROWS / 8, 256>>>(z, ln_g, ln_b, Wb);
    cvt_w<<<320, 256>>>(Wqkv, Wg, Wo);
    // fused: qkv (split bf16) + gate (sigmoid f32) from combined weight
    mma_gemm<<<dim3(NROWS / 128, 4), 256, GEMM_SMEM>>>(
        (const bf16*)pznh, (const bf16*)pznl,
        (const bf16*)pwch, (const bf16*)pwcl,
        (float*)pgate, (bf16*)pqh, (bf16*)pql, 512, 3);
    attn_kernel<<<dim3(2, 4, 256), 256, ATTN_SMEM>>>();
    // out = (gate*o) @ Wo -> f32
    mma_gemm<<<dim3(NROWS / 128, 1), 256, GEMM_SMEM>>>(
        (const bf16*)pgoh, (const bf16*)pgol,
        (const bf16*)pwoh, (const bf16*)pwol,
        out, nullptr, nullptr, 128, 0);
}